// round 12
// baseline (speedup 1.0000x reference)
#include <cuda_runtime.h>
#include <cstdint>

#define NTOK 2304

// ---------------------------------------------------------------------------
// Scratch (device globals — no allocation allowed)
// ---------------------------------------------------------------------------
__device__ uint4 g_wqkv_frag[48 * 16 * 32];            // 768x256 fp16 A-fragments
__device__ uint4 g_wout_frag[16 * 16 * 32];            // 256x256 fp16 A-fragments
__device__ uint4 g_qkv_h[(4u * 768u * NTOK) / 8];      // qkv fp16 [b][768][2304]
__device__ uint4 g_attn_h[(4u * 256u * NTOK) / 8];     // attn out fp16 [b][256][2304]

// ---------------------------------------------------------------------------
__device__ __forceinline__ uint32_t f2h2(float lo, float hi) {
    uint32_t r;
    asm("cvt.rn.f16x2.f32 %0, %1, %2;" : "=r"(r) : "f"(hi), "f"(lo));
    return r;
}
__device__ __forceinline__ uint32_t ex2h2(uint32_t x) {
    uint32_t y;
    asm("ex2.approx.f16x2 %0, %1;" : "=r"(y) : "r"(x));
    return y;
}
__device__ __forceinline__ uint32_t hadd2(uint32_t a, uint32_t b) {
    uint32_t r;
    asm("add.rn.f16x2 %0, %1, %2;" : "=r"(r) : "r"(a), "r"(b));
    return r;
}
__device__ __forceinline__ float h2sum(uint32_t h) {
    float lo, hi;
    asm("{.reg .b16 l, u;\n mov.b32 {l, u}, %2;\n cvt.f32.f16 %0, l;\n cvt.f32.f16 %1, u;}"
        : "=f"(lo), "=f"(hi) : "r"(h));
    return lo + hi;
}
__device__ __forceinline__ uint32_t su(const void* p) {
    return (uint32_t)__cvta_generic_to_shared(p);
}
__device__ __forceinline__ void cpasync16(uint32_t saddr, const void* gp) {
    asm volatile("cp.async.cg.shared.global [%0], [%1], 16;" :: "r"(saddr), "l"(gp));
}
template<int N> __device__ __forceinline__ void cpwait() {
    asm volatile("cp.async.wait_group %0;" :: "n"(N) : "memory");
}
__device__ __forceinline__ void ldsm_x4(uint32_t& r0, uint32_t& r1, uint32_t& r2,
                                        uint32_t& r3, uint32_t addr) {
    asm volatile("ldmatrix.sync.aligned.m8n8.x4.shared.b16 {%0,%1,%2,%3}, [%4];"
                 : "=r"(r0), "=r"(r1), "=r"(r2), "=r"(r3) : "r"(addr));
}
__device__ __forceinline__ void ldsm_x4t(uint32_t& r0, uint32_t& r1, uint32_t& r2,
                                         uint32_t& r3, uint32_t addr) {
    asm volatile("ldmatrix.sync.aligned.m8n8.x4.trans.shared.b16 {%0,%1,%2,%3}, [%4];"
                 : "=r"(r0), "=r"(r1), "=r"(r2), "=r"(r3) : "r"(addr));
}
__device__ __forceinline__ void mma_f16(float* c, const uint32_t* a, const uint32_t* b) {
    asm volatile(
        "mma.sync.aligned.m16n8k16.row.col.f32.f16.f16.f32 "
        "{%0,%1,%2,%3}, {%4,%5,%6,%7}, {%8,%9}, {%0,%1,%2,%3};\n"
        : "+f"(c[0]), "+f"(c[1]), "+f"(c[2]), "+f"(c[3])
        : "r"(a[0]), "r"(a[1]), "r"(a[2]), "r"(a[3]), "r"(b[0]), "r"(b[1]));
}
__device__ __forceinline__ void mma_f16h(uint32_t* d, const uint32_t* a, const uint32_t* b,
                                         const uint32_t* c) {
    asm volatile(
        "mma.sync.aligned.m16n8k16.row.col.f16.f16.f16.f16 "
        "{%0,%1}, {%2,%3,%4,%5}, {%6,%7}, {%8,%9};\n"
        : "=r"(d[0]), "=r"(d[1])
        : "r"(a[0]), "r"(a[1]), "r"(a[2]), "r"(a[3]),
          "r"(b[0]), "r"(b[1]), "r"(c[0]), "r"(c[1]));
}

// ---------------------------------------------------------------------------
// Prep: weights -> fp16 A-fragments (Q rows pre-scaled by log2e/sqrt(d))
// ---------------------------------------------------------------------------
__global__ void prep_frag_kernel(const float* __restrict__ Wq, const float* __restrict__ Wo,
                                 uint4* __restrict__ outq, uint4* __restrict__ outo,
                                 float qscale)
{
    int i = blockIdx.x * 256 + threadIdx.x;
    int lane = i & 31, fj = i >> 5;
    int g = lane >> 2, t = lane & 3;

    const float* W;
    uint4* dst;
    int mi, kj, oidx;
    float s0 = 1.f, s1 = 1.f;
    if (fj < 768) {
        W = Wq; dst = outq; oidx = i;
        mi = fj >> 4; kj = fj & 15;
        int r0 = mi * 16 + g;
        if (r0 < 256) s0 = qscale;
        if (r0 + 8 < 256) s1 = qscale;
    } else {
        W = Wo; dst = outo;
        int fj2 = fj - 768;
        oidx = fj2 * 32 + lane;
        mi = fj2 >> 4; kj = fj2 & 15;
    }
    int r0 = mi * 16 + g, r1 = r0 + 8;
    int c0 = kj * 16 + 2 * t, c1 = c0 + 8;
    const float* w0 = W + (size_t)r0 * 256;
    const float* w1 = W + (size_t)r1 * 256;
    uint4 o;
    o.x = f2h2(w0[c0] * s0, w0[c0 + 1] * s0);
    o.y = f2h2(w1[c0] * s1, w1[c0 + 1] * s1);
    o.z = f2h2(w0[c1] * s0, w0[c1 + 1] * s0);
    o.w = f2h2(w1[c1] * s1, w1[c1 + 1] * s1);
    dst[oidx] = o;
}

// ---------------------------------------------------------------------------
// GEMM 1: C[z] (fp16) = W (fp16 A-frags) @ B[z] (KxN fp32). (r10, passing)
// ---------------------------------------------------------------------------
__global__ void __launch_bounds__(256, 2) gemm_f32b_kernel(
    const uint4* __restrict__ Afrag, const float* __restrict__ Bf_all,
    uint16_t* __restrict__ Ch_all, int N, int K)
{
    __shared__ uint32_t Bs[2][32 * 68];

    const int Kt = K >> 4, KB = K >> 5;
    const int M = 64 * gridDim.y;
    const int m0 = blockIdx.y * 64, n0 = blockIdx.x * 128, z = blockIdx.z;
    const int tid = threadIdx.x, w = tid >> 5, lane = tid & 31, g = lane >> 2, t = lane & 3;
    const int wm = (w >> 2) * 32, wn = (w & 3) * 32;
    const int miBase = (m0 + wm) >> 4;

    const float* Bf = Bf_all + (size_t)z * K * N;

    float acc[2][4][4];
#pragma unroll
    for (int mt = 0; mt < 2; mt++)
#pragma unroll
        for (int nt = 0; nt < 4; nt++)
#pragma unroll
            for (int r = 0; r < 4; r++) acc[mt][nt][r] = 0.f;

    float4 sf[4];
#pragma unroll
    for (int it = 0; it < 4; it++) {
        int r = (tid >> 5) + it * 8;
        sf[it] = *(const float4*)(Bf + (size_t)r * N + n0 + lane * 4);
    }

    for (int kb = 0; kb < KB; kb++) {
        const int cur = kb & 1;
#pragma unroll
        for (int it = 0; it < 4; it++) {
            int r = (tid >> 5) + it * 8;
            *(uint2*)&Bs[cur][r * 68 + lane * 2] =
                make_uint2(f2h2(sf[it].x, sf[it].y), f2h2(sf[it].z, sf[it].w));
        }
        __syncthreads();

        if (kb + 1 < KB) {
            const float* Bn = Bf + (size_t)((kb + 1) * 32) * N;
#pragma unroll
            for (int it = 0; it < 4; it++) {
                int r = (tid >> 5) + it * 8;
                sf[it] = *(const float4*)(Bn + (size_t)r * N + n0 + lane * 4);
            }
        }

        uint4 af[2][2];
#pragma unroll
        for (int mt = 0; mt < 2; mt++)
#pragma unroll
            for (int ks = 0; ks < 2; ks++)
                af[mt][ks] = Afrag[((size_t)(miBase + mt) * Kt + kb * 2 + ks) * 32 + lane];

#pragma unroll
        for (int ks = 0; ks < 2; ks++) {
            uint32_t bf[4][2];
#pragma unroll
            for (int np = 0; np < 2; np++) {
                uint32_t addrh = (uint32_t)((ks * 16 + ((lane >> 3) & 1) * 8 + (lane & 7)) * 136
                                          + (wn + np * 16 + (lane >> 4) * 8));
                ldsm_x4t(bf[2 * np][0], bf[2 * np][1], bf[2 * np + 1][0], bf[2 * np + 1][1],
                         su(&Bs[cur][0]) + addrh * 2);
            }
#pragma unroll
            for (int mt = 0; mt < 2; mt++)
#pragma unroll
                for (int nt = 0; nt < 4; nt++)
                    mma_f16(acc[mt][nt], (const uint32_t*)&af[mt][ks], bf[nt]);
        }
    }

    uint16_t* Ch = Ch_all + (size_t)z * M * N;
#pragma unroll
    for (int mt = 0; mt < 2; mt++) {
        int ra = m0 + wm + mt * 16 + g;
#pragma unroll
        for (int nt = 0; nt < 4; nt++) {
            int col = n0 + wn + nt * 8 + 2 * t;
            *(uint32_t*)&Ch[(size_t)ra * N + col] = f2h2(acc[mt][nt][0], acc[mt][nt][1]);
            *(uint32_t*)&Ch[(size_t)(ra + 8) * N + col] = f2h2(acc[mt][nt][2], acc[mt][nt][3]);
        }
    }
}

// ---------------------------------------------------------------------------
// GEMM 3: C[z] (fp32, +bias) = W (fp16 A-frags) @ B[z] (KxN fp16). K=256.
// ALL 8 K-stages resident (69.6 KB dynamic smem); all cp.async issued up
// front; per stage wait_group(7-kb)+sync -> later-stage latency fully hidden.
// ---------------------------------------------------------------------------
__global__ void __launch_bounds__(256, 2) gemm_f16b_kernel(
    const uint4* __restrict__ Afrag, const uint16_t* __restrict__ Bh_all,
    float* __restrict__ Cf_all, const float* __restrict__ bias, int N)
{
    extern __shared__ uint32_t Bsd[];  // [8][32*68]

    const int K = 256, Kt = 16;
    const int M = 64 * gridDim.y;
    const int m0 = blockIdx.y * 64, n0 = blockIdx.x * 128, z = blockIdx.z;
    const int tid = threadIdx.x, w = tid >> 5, lane = tid & 31, g = lane >> 2, t = lane & 3;
    const int wm = (w >> 2) * 32, wn = (w & 3) * 32;
    const int miBase = (m0 + wm) >> 4;

    const uint16_t* Bh = Bh_all + (size_t)z * K * N;

    float acc[2][4][4];
#pragma unroll
    for (int mt = 0; mt < 2; mt++)
#pragma unroll
        for (int nt = 0; nt < 4; nt++)
#pragma unroll
            for (int r = 0; r < 4; r++) acc[mt][nt][r] = 0.f;

    // issue all 8 stages up front (one commit group each, FIFO completion)
#pragma unroll
    for (int kb = 0; kb < 8; kb++) {
#pragma unroll
        for (int it = 0; it < 2; it++) {
            int idx = tid + it * 256;
            int r = idx >> 4, c16 = idx & 15;
            cpasync16(su(&Bsd[kb * 2176 + r * 68 + c16 * 4]),
                      Bh + (size_t)(kb * 32 + r) * N + n0 + c16 * 8);
        }
        asm volatile("cp.async.commit_group;");
    }

    uint4 afA[2][2], afB[2][2];
#pragma unroll
    for (int mt = 0; mt < 2; mt++)
#pragma unroll
        for (int ks = 0; ks < 2; ks++)
            afA[mt][ks] = Afrag[((size_t)(miBase + mt) * Kt + ks) * 32 + lane];

#pragma unroll
    for (int kb = 0; kb < 8; kb++) {
        if      (kb == 0) cpwait<7>();
        else if (kb == 1) cpwait<6>();
        else if (kb == 2) cpwait<5>();
        else if (kb == 3) cpwait<4>();
        else if (kb == 4) cpwait<3>();
        else if (kb == 5) cpwait<2>();
        else if (kb == 6) cpwait<1>();
        else              cpwait<0>();
        __syncthreads();

        if (kb + 1 < 8) {
#pragma unroll
            for (int mt = 0; mt < 2; mt++)
#pragma unroll
                for (int ks = 0; ks < 2; ks++)
                    afB[mt][ks] = Afrag[((size_t)(miBase + mt) * Kt + (kb + 1) * 2 + ks) * 32 + lane];
        }

#pragma unroll
        for (int ks = 0; ks < 2; ks++) {
            uint32_t bf[4][2];
#pragma unroll
            for (int np = 0; np < 2; np++) {
                uint32_t addrh = (uint32_t)((ks * 16 + ((lane >> 3) & 1) * 8 + (lane & 7)) * 136
                                          + (wn + np * 16 + (lane >> 4) * 8));
                ldsm_x4t(bf[2 * np][0], bf[2 * np][1], bf[2 * np + 1][0], bf[2 * np + 1][1],
                         su(&Bsd[kb * 2176]) + addrh * 2);
            }
#pragma unroll
            for (int mt = 0; mt < 2; mt++)
#pragma unroll
                for (int nt = 0; nt < 4; nt++)
                    mma_f16(acc[mt][nt], (const uint32_t*)&afA[mt][ks], bf[nt]);
        }
#pragma unroll
        for (int mt = 0; mt < 2; mt++)
#pragma unroll
            for (int ks = 0; ks < 2; ks++)
                afA[mt][ks] = afB[mt][ks];
    }

    float* Cf = Cf_all + (size_t)z * M * N;
#pragma unroll
    for (int mt = 0; mt < 2; mt++) {
        int ra = m0 + wm + mt * 16 + g;
        float ba = bias[ra], bb = bias[ra + 8];
#pragma unroll
        for (int nt = 0; nt < 4; nt++) {
            int col = n0 + wn + nt * 8 + 2 * t;
            *(float2*)(Cf + (size_t)ra * N + col) =
                make_float2(acc[mt][nt][0] + ba, acc[mt][nt][1] + ba);
            *(float2*)(Cf + (size_t)(ra + 8) * N + col) =
                make_float2(acc[mt][nt][2] + bb, acc[mt][nt][3] + bb);
        }
    }
}

// ---------------------------------------------------------------------------
// Flash attention, SOFTWARE-PIPELINED across j-tiles. Per CTA: (b,h) x 128
// q-rows. 8 warps: jg=w&1 (j-half, Bc=64), rg=w>>1 (32 q-rows).
// Steady state per tile: wait/sync -> prefetch jb+3 -> QK(jb+1)->sc2 (tensor
// burst) -> ex2(sc)->pb (MUFU, hidden under QK) -> PV(jb) (tensor burst).
// The per-tile exp drain that idled the tensor pipe in r6-r10 is overlapped.
// cp.async ring-4; FIFO waits: group jb+1 completes at wait_group 1.
// ---------------------------------------------------------------------------
__global__ void __launch_bounds__(256, 2) attn_kernel(const uint16_t* __restrict__ qkvh,
                                                      uint16_t* __restrict__ oh)
{
    extern __shared__ uint32_t sm[];
    uint32_t* Qs  = sm;                                      // [32][68]  (2176 w)
    uint32_t* KVb = sm + 2176;                               // [4][2][1152] (9216 w)
    float (*redO)[32][33] = (float(*)[32][33])(sm + 11392);  // 4224 w
    float (*redL)[4][32]  = (float(*)[4][32])(sm + 15616);   // 256 w

    const int bh = blockIdx.y, b = bh >> 3, h = bh & 7;
    const int i0 = blockIdx.x * 128;
    const uint16_t* Qg = qkvh + ((size_t)b * 768 + h * 32) * NTOK;
    const uint16_t* Kg = Qg + (size_t)256 * NTOK;
    const uint16_t* Vg = Qg + (size_t)512 * NTOK;
    const int tid = threadIdx.x, w = tid >> 5, lane = tid & 31, g = lane >> 2, t = lane & 3;
    const int rg = w >> 1, jg = w & 1;
    const int ibase = rg * 32, jcol = jg * 32;
    const int krow = tid >> 3, kch = tid & 7;

    auto issue_tile = [&](int jb) {
        const int j0 = jb * 64;
        uint32_t base = su(KVb + (jb & 3) * 2304);
        cpasync16(base + (uint32_t)(krow * 36 + kch * 4) * 4,
                  Kg + (size_t)krow * NTOK + j0 + kch * 8);
        cpasync16(base + (uint32_t)(1152 + krow * 36 + kch * 4) * 4,
                  Vg + (size_t)krow * NTOK + j0 + kch * 8);
        asm volatile("cp.async.commit_group;");
    };

    // prologue: 3 tiles in flight + Q copy
    issue_tile(0);
    issue_tile(1);
#pragma unroll
    for (int it = 0; it < 2; it++) {
        int idx = tid + it * 256;
        int d = idx >> 4, c = idx & 15;
        uint4 v = *(const uint4*)(Qg + (size_t)d * NTOK + i0 + c * 8);
        *(uint4*)&Qs[d * 68 + c * 4] = v;
    }
    issue_tile(2);
    __syncthreads();

    // Q A-fragments (reused all 36 tiles)
    uint32_t qf[2][2][4];
#pragma unroll
    for (int mt = 0; mt < 2; mt++)
#pragma unroll
        for (int ks = 0; ks < 2; ks++) {
            uint32_t addrh = (uint32_t)((ks * 16 + (lane >> 4) * 8 + (lane & 7)) * 136
                                      + (ibase + mt * 16 + ((lane >> 3) & 1) * 8));
            ldsm_x4t(qf[mt][ks][0], qf[mt][ks][1], qf[mt][ks][2], qf[mt][ks][3],
                     su(Qs) + addrh * 2);
        }

    float oacc[2][4][4];
#pragma unroll
    for (int dvt = 0; dvt < 2; dvt++)
#pragma unroll
        for (int it = 0; it < 4; it++)
#pragma unroll
            for (int r = 0; r < 4; r++) oacc[dvt][it][r] = 0.f;
    float lsum[4] = {0.f, 0.f, 0.f, 0.f};
    const uint32_t zz[2] = {0u, 0u};

    // QK for tile jb -> S fragments (fp16 accum); kfr loaded per ks (8 regs live)
    auto qk_tile = [&](int jb, uint32_t (&sc)[2][4][2]) {
        const uint32_t Ksm = su(KVb + (jb & 3) * 2304);
#pragma unroll
        for (int ks = 0; ks < 2; ks++) {
            uint32_t kf[4][2];
#pragma unroll
            for (int np = 0; np < 2; np++) {
                uint32_t addrh = (uint32_t)((ks * 16 + ((lane >> 3) & 1) * 8 + (lane & 7)) * 72
                                          + (jcol + np * 16 + (lane >> 4) * 8));
                ldsm_x4t(kf[2 * np][0], kf[2 * np][1], kf[2 * np + 1][0], kf[2 * np + 1][1],
                         Ksm + addrh * 2);
            }
            if (ks == 0) {
#pragma unroll
                for (int jt = 0; jt < 4; jt++) {
                    mma_f16h(sc[0][jt], qf[0][0], kf[jt], zz);
                    mma_f16h(sc[1][jt], qf[1][0], kf[jt], zz);
                }
            } else {
#pragma unroll
                for (int jt = 0; jt < 4; jt++) {
                    mma_f16h(sc[0][jt], qf[0][1], kf[jt], sc[0][jt]);
                    mma_f16h(sc[1][jt], qf[1][1], kf[jt], sc[1][jt]);
                }
            }
        }
    };

    // One pipeline step: consume S(jb) (in scur), produce S(jb+1) (into snext)
    auto step = [&](int jb, uint32_t (&scur)[2][4][2], uint32_t (&snext)[2][4][2]) {
        if (jb < 34)       { cpwait<1>(); }
        else if (jb == 34) { cpwait<0>(); }
        __syncthreads();
        if (jb + 3 < 36) issue_tile(jb + 3);

        // QK for the NEXT tile first — tensor pipe stays busy while we exp
        if (jb < 35) qk_tile(jb + 1, snext);

        // P^T = 2^S for current tile (MUFU; overlaps in-flight QK mmas)
        uint32_t pb[2][4][2];
#pragma unroll
        for (int kk = 0; kk < 2; kk++)
#pragma unroll
            for (int mt = 0; mt < 2; mt++) {
                pb[kk][2 * mt][0]     = ex2h2(scur[mt][2 * kk][0]);
                pb[kk][2 * mt][1]     = ex2h2(scur[mt][2 * kk + 1][0]);
                pb[kk][2 * mt + 1][0] = ex2h2(scur[mt][2 * kk][1]);
                pb[kk][2 * mt + 1][1] = ex2h2(scur[mt][2 * kk + 1][1]);
            }
#pragma unroll
        for (int it = 0; it < 4; it++) {
            uint32_t hs = hadd2(hadd2(pb[0][it][0], pb[0][it][1]),
                                hadd2(pb[1][it][0], pb[1][it][1]));
            lsum[it] += h2sum(hs);
        }

        // PV for current tile; va loaded per kk (8 regs live)
        const uint32_t Vsm = su(KVb + (jb & 3) * 2304 + 1152);
#pragma unroll
        for (int kk = 0; kk < 2; kk++) {
            uint32_t va0[4], va1[4];
            {
                uint32_t a0 = (uint32_t)((0 * 16 + ((lane >> 3) & 1) * 8 + (lane & 7)) * 72
                                       + (jcol + kk * 16 + (lane >> 4) * 8));
                uint32_t a1 = (uint32_t)((1 * 16 + ((lane >> 3) & 1) * 8 + (lane & 7)) * 72
                                       + (jcol + kk * 16 + (lane >> 4) * 8));
                ldsm_x4(va0[0], va0[1], va0[2], va0[3], Vsm + a0 * 2);
                ldsm_x4(va1[0], va1[1], va1[2], va1[3], Vsm + a1 * 2);
            }
#pragma unroll
            for (int it = 0; it < 4; it++) {
                mma_f16(oacc[0][it], va0, pb[kk][it]);
                mma_f16(oacc[1][it], va1, pb[kk][it]);
            }
        }
    };

    // pipeline prologue: S(0)
    uint32_t scA[2][4][2], scB[2][4][2];
    cpwait<2>();
    __syncthreads();
    qk_tile(0, scA);

    // main loop: 2 tiles per iteration (register role swap, no copies)
    for (int jb = 0; jb < 36; jb += 2) {
        step(jb, scA, scB);
        step(jb + 1, scB, scA);
    }

    // Quad-reduce row sums over t
#pragma unroll
    for (int it = 0; it < 4; it++) {
        lsum[it] += __shfl_xor_sync(0xffffffffu, lsum[it], 1);
        lsum[it] += __shfl_xor_sync(0xffffffffu, lsum[it], 2);
    }

    // Cross-jg reduction
    __syncthreads();
    if (t == 0) {
#pragma unroll
        for (int it = 0; it < 4; it++)
            redL[jg][rg][it * 8 + g] = lsum[it];
    }
    if (jg == 1) {
#pragma unroll
        for (int dvt = 0; dvt < 2; dvt++)
#pragma unroll
            for (int it = 0; it < 4; it++) {
                int dv = dvt * 16 + g, ii = it * 8 + 2 * t;
                redO[rg][dv][ii]         = oacc[dvt][it][0];
                redO[rg][dv][ii + 1]     = oacc[dvt][it][1];
                redO[rg][dv + 8][ii]     = oacc[dvt][it][2];
                redO[rg][dv + 8][ii + 1] = oacc[dvt][it][3];
            }
    }
    __syncthreads();
    if (jg == 0) {
        uint16_t* Ob = oh + ((size_t)b * 256 + h * 32) * NTOK;
#pragma unroll
        for (int it = 0; it < 4; it++) {
            int ii = it * 8 + 2 * t;
            float inv0 = 1.f / (redL[0][rg][ii] + redL[1][rg][ii]);
            float inv1 = 1.f / (redL[0][rg][ii + 1] + redL[1][rg][ii + 1]);
            int ig = i0 + ibase + ii;
#pragma unroll
            for (int dvt = 0; dvt < 2; dvt++) {
                int dv = dvt * 16 + g;
                float o0 = (oacc[dvt][it][0] + redO[rg][dv][ii]) * inv0;
                float o1 = (oacc[dvt][it][1] + redO[rg][dv][ii + 1]) * inv1;
                *(uint32_t*)&Ob[(size_t)dv * NTOK + ig] = f2h2(o0, o1);
                float o2 = (oacc[dvt][it][2] + redO[rg][dv + 8][ii]) * inv0;
                float o3 = (oacc[dvt][it][3] + redO[rg][dv + 8][ii + 1]) * inv1;
                *(uint32_t*)&Ob[(size_t)(dv + 8) * NTOK + ig] = f2h2(o2, o3);
            }
        }
    }
}

// ---------------------------------------------------------------------------

extern "C" void kernel_launch(void* const* d_in, const int* in_sizes, int n_in,
                              void* d_out, int out_size)
{
    const float* x     = (const float*)d_in[0];  // (4,256,48,48)
    const float* w_qkv = (const float*)d_in[1];  // (768,256)
    const float* w_out = (const float*)d_in[2];  // (256,256)
    const float* b_out = (const float*)d_in[3];  // (256)
    float* out = (float*)d_out;                  // (4,256,48,48)

    uint4 *wqkvF = nullptr, *woutF = nullptr, *qkvH = nullptr, *attnH = nullptr;
    cudaGetSymbolAddress((void**)&wqkvF, g_wqkv_frag);
    cudaGetSymbolAddress((void**)&woutF, g_wout_frag);
    cudaGetSymbolAddress((void**)&qkvH, g_qkv_h);
    cudaGetSymbolAddress((void**)&attnH, g_attn_h);

    const float qscale = 0.25507607192159975f;  // log2(e)/sqrt(32)
    const int attn_smem = 15872 * 4;            // 63488 B
    const int g3_smem = 8 * 2176 * 4;           // 69632 B

    cudaFuncSetAttribute(attn_kernel, cudaFuncAttributeMaxDynamicSharedMemorySize,
                         attn_smem);
    cudaFuncSetAttribute(gemm_f16b_kernel, cudaFuncAttributeMaxDynamicSharedMemorySize,
                         g3_smem);

    // 0) weight prep
    prep_frag_kernel<<<128, 256>>>(w_qkv, w_out, wqkvF, woutF, qscale);

    // 1) QKV projection (fp32 x -> fp16 qkv)  (864 CTAs)
    gemm_f32b_kernel<<<dim3(18, 12, 4), 256>>>(wqkvF, x, (uint16_t*)qkvH, NTOK, 256);
    // 2) Pipelined flash attention -> fp16 attn  (576 CTAs)
    attn_kernel<<<dim3(18, 32), 256, attn_smem>>>((const uint16_t*)qkvH, (uint16_t*)attnH);
    // 3) Output projection + bias -> fp32 out  (288 CTAs)
    gemm_f16b_kernel<<<dim3(18, 4, 4), 256, g3_smem>>>(woutF, (const uint16_t*)attnH,
                                                       out, b_out, NTOK);
}

// round 13
// speedup vs baseline: 1.0389x; 1.0389x over previous
#include <cuda_runtime.h>
#include <cstdint>

#define NTOK 2304

// ---------------------------------------------------------------------------
// Scratch (device globals — no allocation allowed)
// ---------------------------------------------------------------------------
__device__ uint4 g_wqkv_frag[48 * 16 * 32];            // 768x256 fp16 A-fragments
__device__ uint4 g_wout_frag[16 * 16 * 32];            // 256x256 fp16 A-fragments
__device__ uint4 g_qkv_h[(4u * 768u * NTOK) / 8];      // qkv fp16 [b][768][2304]
__device__ uint4 g_attn_h[(4u * 256u * NTOK) / 8];     // attn out fp16 [b][256][2304]

// ---------------------------------------------------------------------------
__device__ __forceinline__ uint32_t f2h2(float lo, float hi) {
    uint32_t r;
    asm("cvt.rn.f16x2.f32 %0, %1, %2;" : "=r"(r) : "f"(hi), "f"(lo));
    return r;
}
__device__ __forceinline__ uint32_t ex2h2(uint32_t x) {
    uint32_t y;
    asm("ex2.approx.f16x2 %0, %1;" : "=r"(y) : "r"(x));
    return y;
}
__device__ __forceinline__ uint32_t hadd2(uint32_t a, uint32_t b) {
    uint32_t r;
    asm("add.rn.f16x2 %0, %1, %2;" : "=r"(r) : "r"(a), "r"(b));
    return r;
}
__device__ __forceinline__ float h2sum(uint32_t h) {
    float lo, hi;
    asm("{.reg .b16 l, u;\n mov.b32 {l, u}, %2;\n cvt.f32.f16 %0, l;\n cvt.f32.f16 %1, u;}"
        : "=f"(lo), "=f"(hi) : "r"(h));
    return lo + hi;
}
__device__ __forceinline__ uint32_t su(const void* p) {
    return (uint32_t)__cvta_generic_to_shared(p);
}
__device__ __forceinline__ void cpasync16(uint32_t saddr, const void* gp) {
    asm volatile("cp.async.cg.shared.global [%0], [%1], 16;" :: "r"(saddr), "l"(gp));
}
template<int N> __device__ __forceinline__ void cpwait() {
    asm volatile("cp.async.wait_group %0;" :: "n"(N) : "memory");
}
__device__ __forceinline__ void ldsm_x4(uint32_t& r0, uint32_t& r1, uint32_t& r2,
                                        uint32_t& r3, uint32_t addr) {
    asm volatile("ldmatrix.sync.aligned.m8n8.x4.shared.b16 {%0,%1,%2,%3}, [%4];"
                 : "=r"(r0), "=r"(r1), "=r"(r2), "=r"(r3) : "r"(addr));
}
__device__ __forceinline__ void ldsm_x4t(uint32_t& r0, uint32_t& r1, uint32_t& r2,
                                         uint32_t& r3, uint32_t addr) {
    asm volatile("ldmatrix.sync.aligned.m8n8.x4.trans.shared.b16 {%0,%1,%2,%3}, [%4];"
                 : "=r"(r0), "=r"(r1), "=r"(r2), "=r"(r3) : "r"(addr));
}
__device__ __forceinline__ void mma_f16(float* c, const uint32_t* a, const uint32_t* b) {
    asm volatile(
        "mma.sync.aligned.m16n8k16.row.col.f32.f16.f16.f32 "
        "{%0,%1,%2,%3}, {%4,%5,%6,%7}, {%8,%9}, {%0,%1,%2,%3};\n"
        : "+f"(c[0]), "+f"(c[1]), "+f"(c[2]), "+f"(c[3])
        : "r"(a[0]), "r"(a[1]), "r"(a[2]), "r"(a[3]), "r"(b[0]), "r"(b[1]));
}
__device__ __forceinline__ void mma_f16h(uint32_t* d, const uint32_t* a, const uint32_t* b,
                                         const uint32_t* c) {
    asm volatile(
        "mma.sync.aligned.m16n8k16.row.col.f16.f16.f16.f16 "
        "{%0,%1}, {%2,%3,%4,%5}, {%6,%7}, {%8,%9};\n"
        : "=r"(d[0]), "=r"(d[1])
        : "r"(a[0]), "r"(a[1]), "r"(a[2]), "r"(a[3]),
          "r"(b[0]), "r"(b[1]), "r"(c[0]), "r"(c[1]));
}

// ---------------------------------------------------------------------------
// Prep: weights -> fp16 A-fragments (Q rows pre-scaled by log2e/sqrt(d))
// ---------------------------------------------------------------------------
__global__ void prep_frag_kernel(const float* __restrict__ Wq, const float* __restrict__ Wo,
                                 uint4* __restrict__ outq, uint4* __restrict__ outo,
                                 float qscale)
{
    int i = blockIdx.x * 256 + threadIdx.x;
    int lane = i & 31, fj = i >> 5;
    int g = lane >> 2, t = lane & 3;

    const float* W;
    uint4* dst;
    int mi, kj, oidx;
    float s0 = 1.f, s1 = 1.f;
    if (fj < 768) {
        W = Wq; dst = outq; oidx = i;
        mi = fj >> 4; kj = fj & 15;
        int r0 = mi * 16 + g;
        if (r0 < 256) s0 = qscale;
        if (r0 + 8 < 256) s1 = qscale;
    } else {
        W = Wo; dst = outo;
        int fj2 = fj - 768;
        oidx = fj2 * 32 + lane;
        mi = fj2 >> 4; kj = fj2 & 15;
    }
    int r0 = mi * 16 + g, r1 = r0 + 8;
    int c0 = kj * 16 + 2 * t, c1 = c0 + 8;
    const float* w0 = W + (size_t)r0 * 256;
    const float* w1 = W + (size_t)r1 * 256;
    uint4 o;
    o.x = f2h2(w0[c0] * s0, w0[c0 + 1] * s0);
    o.y = f2h2(w1[c0] * s1, w1[c0 + 1] * s1);
    o.z = f2h2(w0[c1] * s0, w0[c1 + 1] * s0);
    o.w = f2h2(w1[c1] * s1, w1[c1 + 1] * s1);
    dst[oidx] = o;
}

// ---------------------------------------------------------------------------
// GEMM 1: C[z] (fp16) = W (fp16 A-frags) @ B[z] (KxN fp32). (r10, passing)
// ---------------------------------------------------------------------------
__global__ void __launch_bounds__(256, 2) gemm_f32b_kernel(
    const uint4* __restrict__ Afrag, const float* __restrict__ Bf_all,
    uint16_t* __restrict__ Ch_all, int N, int K)
{
    __shared__ uint32_t Bs[2][32 * 68];

    const int Kt = K >> 4, KB = K >> 5;
    const int M = 64 * gridDim.y;
    const int m0 = blockIdx.y * 64, n0 = blockIdx.x * 128, z = blockIdx.z;
    const int tid = threadIdx.x, w = tid >> 5, lane = tid & 31, g = lane >> 2, t = lane & 3;
    const int wm = (w >> 2) * 32, wn = (w & 3) * 32;
    const int miBase = (m0 + wm) >> 4;

    const float* Bf = Bf_all + (size_t)z * K * N;

    float acc[2][4][4];
#pragma unroll
    for (int mt = 0; mt < 2; mt++)
#pragma unroll
        for (int nt = 0; nt < 4; nt++)
#pragma unroll
            for (int r = 0; r < 4; r++) acc[mt][nt][r] = 0.f;

    float4 sf[4];
#pragma unroll
    for (int it = 0; it < 4; it++) {
        int r = (tid >> 5) + it * 8;
        sf[it] = *(const float4*)(Bf + (size_t)r * N + n0 + lane * 4);
    }

    for (int kb = 0; kb < KB; kb++) {
        const int cur = kb & 1;
#pragma unroll
        for (int it = 0; it < 4; it++) {
            int r = (tid >> 5) + it * 8;
            *(uint2*)&Bs[cur][r * 68 + lane * 2] =
                make_uint2(f2h2(sf[it].x, sf[it].y), f2h2(sf[it].z, sf[it].w));
        }
        __syncthreads();

        if (kb + 1 < KB) {
            const float* Bn = Bf + (size_t)((kb + 1) * 32) * N;
#pragma unroll
            for (int it = 0; it < 4; it++) {
                int r = (tid >> 5) + it * 8;
                sf[it] = *(const float4*)(Bn + (size_t)r * N + n0 + lane * 4);
            }
        }

        uint4 af[2][2];
#pragma unroll
        for (int mt = 0; mt < 2; mt++)
#pragma unroll
            for (int ks = 0; ks < 2; ks++)
                af[mt][ks] = Afrag[((size_t)(miBase + mt) * Kt + kb * 2 + ks) * 32 + lane];

#pragma unroll
        for (int ks = 0; ks < 2; ks++) {
            uint32_t bf[4][2];
#pragma unroll
            for (int np = 0; np < 2; np++) {
                uint32_t addrh = (uint32_t)((ks * 16 + ((lane >> 3) & 1) * 8 + (lane & 7)) * 136
                                          + (wn + np * 16 + (lane >> 4) * 8));
                ldsm_x4t(bf[2 * np][0], bf[2 * np][1], bf[2 * np + 1][0], bf[2 * np + 1][1],
                         su(&Bs[cur][0]) + addrh * 2);
            }
#pragma unroll
            for (int mt = 0; mt < 2; mt++)
#pragma unroll
                for (int nt = 0; nt < 4; nt++)
                    mma_f16(acc[mt][nt], (const uint32_t*)&af[mt][ks], bf[nt]);
        }
    }

    uint16_t* Ch = Ch_all + (size_t)z * M * N;
#pragma unroll
    for (int mt = 0; mt < 2; mt++) {
        int ra = m0 + wm + mt * 16 + g;
#pragma unroll
        for (int nt = 0; nt < 4; nt++) {
            int col = n0 + wn + nt * 8 + 2 * t;
            *(uint32_t*)&Ch[(size_t)ra * N + col] = f2h2(acc[mt][nt][0], acc[mt][nt][1]);
            *(uint32_t*)&Ch[(size_t)(ra + 8) * N + col] = f2h2(acc[mt][nt][2], acc[mt][nt][3]);
        }
    }
}

// ---------------------------------------------------------------------------
// GEMM 3: C[z] (fp32, +bias) = W (fp16 A-frags) @ B[z] (KxN fp16). K=256.
// ALL 8 K-stages resident (r12 version, measured 10.2us).
// ---------------------------------------------------------------------------
__global__ void __launch_bounds__(256, 2) gemm_f16b_kernel(
    const uint4* __restrict__ Afrag, const uint16_t* __restrict__ Bh_all,
    float* __restrict__ Cf_all, const float* __restrict__ bias, int N)
{
    extern __shared__ uint32_t Bsd[];  // [8][32*68]

    const int K = 256, Kt = 16;
    const int M = 64 * gridDim.y;
    const int m0 = blockIdx.y * 64, n0 = blockIdx.x * 128, z = blockIdx.z;
    const int tid = threadIdx.x, w = tid >> 5, lane = tid & 31, g = lane >> 2, t = lane & 3;
    const int wm = (w >> 2) * 32, wn = (w & 3) * 32;
    const int miBase = (m0 + wm) >> 4;

    const uint16_t* Bh = Bh_all + (size_t)z * K * N;

    float acc[2][4][4];
#pragma unroll
    for (int mt = 0; mt < 2; mt++)
#pragma unroll
        for (int nt = 0; nt < 4; nt++)
#pragma unroll
            for (int r = 0; r < 4; r++) acc[mt][nt][r] = 0.f;

#pragma unroll
    for (int kb = 0; kb < 8; kb++) {
#pragma unroll
        for (int it = 0; it < 2; it++) {
            int idx = tid + it * 256;
            int r = idx >> 4, c16 = idx & 15;
            cpasync16(su(&Bsd[kb * 2176 + r * 68 + c16 * 4]),
                      Bh + (size_t)(kb * 32 + r) * N + n0 + c16 * 8);
        }
        asm volatile("cp.async.commit_group;");
    }

    uint4 afA[2][2], afB[2][2];
#pragma unroll
    for (int mt = 0; mt < 2; mt++)
#pragma unroll
        for (int ks = 0; ks < 2; ks++)
            afA[mt][ks] = Afrag[((size_t)(miBase + mt) * Kt + ks) * 32 + lane];

#pragma unroll
    for (int kb = 0; kb < 8; kb++) {
        if      (kb == 0) cpwait<7>();
        else if (kb == 1) cpwait<6>();
        else if (kb == 2) cpwait<5>();
        else if (kb == 3) cpwait<4>();
        else if (kb == 4) cpwait<3>();
        else if (kb == 5) cpwait<2>();
        else if (kb == 6) cpwait<1>();
        else              cpwait<0>();
        __syncthreads();

        if (kb + 1 < 8) {
#pragma unroll
            for (int mt = 0; mt < 2; mt++)
#pragma unroll
                for (int ks = 0; ks < 2; ks++)
                    afB[mt][ks] = Afrag[((size_t)(miBase + mt) * Kt + (kb + 1) * 2 + ks) * 32 + lane];
        }

#pragma unroll
        for (int ks = 0; ks < 2; ks++) {
            uint32_t bf[4][2];
#pragma unroll
            for (int np = 0; np < 2; np++) {
                uint32_t addrh = (uint32_t)((ks * 16 + ((lane >> 3) & 1) * 8 + (lane & 7)) * 136
                                          + (wn + np * 16 + (lane >> 4) * 8));
                ldsm_x4t(bf[2 * np][0], bf[2 * np][1], bf[2 * np + 1][0], bf[2 * np + 1][1],
                         su(&Bsd[kb * 2176]) + addrh * 2);
            }
#pragma unroll
            for (int mt = 0; mt < 2; mt++)
#pragma unroll
                for (int nt = 0; nt < 4; nt++)
                    mma_f16(acc[mt][nt], (const uint32_t*)&afA[mt][ks], bf[nt]);
        }
#pragma unroll
        for (int mt = 0; mt < 2; mt++)
#pragma unroll
            for (int ks = 0; ks < 2; ks++)
                afA[mt][ks] = afB[mt][ks];
    }

    float* Cf = Cf_all + (size_t)z * M * N;
#pragma unroll
    for (int mt = 0; mt < 2; mt++) {
        int ra = m0 + wm + mt * 16 + g;
        float ba = bias[ra], bb = bias[ra + 8];
#pragma unroll
        for (int nt = 0; nt < 4; nt++) {
            int col = n0 + wn + nt * 8 + 2 * t;
            *(float2*)(Cf + (size_t)ra * N + col) =
                make_float2(acc[mt][nt][0] + ba, acc[mt][nt][1] + ba);
            *(float2*)(Cf + (size_t)(ra + 8) * N + col) =
                make_float2(acc[mt][nt][2] + bb, acc[mt][nt][3] + bb);
        }
    }
}

// ---------------------------------------------------------------------------
// Flash attention (r10 body). Ring-6 KV buffers, ONE __syncthreads per TWO
// tiles. Pair loop: wait<2> (groups jb, jb+1 complete) -> sync (visibility)
// -> issue jb+4, jb+5 (buffers last read at tiles jb-2 / jb-1, both before
// this pair's sync) -> compute jb, jb+1. Tail pair uses wait<0>.
// ---------------------------------------------------------------------------
__global__ void __launch_bounds__(256, 2) attn_kernel(const uint16_t* __restrict__ qkvh,
                                                      uint16_t* __restrict__ oh)
{
    extern __shared__ uint32_t sm[];
    uint32_t* Qs  = sm;                                      // [32][68]  (2176 w)
    uint32_t* KVb = sm + 2176;                               // [6][2][1152] (13824 w)
    float (*redO)[32][33] = (float(*)[32][33])(sm + 16000);  // 4224 w
    float (*redL)[4][32]  = (float(*)[4][32])(sm + 20224);   // 256 w

    const int bh = blockIdx.y, b = bh >> 3, h = bh & 7;
    const int i0 = blockIdx.x * 128;
    const uint16_t* Qg = qkvh + ((size_t)b * 768 + h * 32) * NTOK;
    const uint16_t* Kg = Qg + (size_t)256 * NTOK;
    const uint16_t* Vg = Qg + (size_t)512 * NTOK;
    const int tid = threadIdx.x, w = tid >> 5, lane = tid & 31, g = lane >> 2, t = lane & 3;
    const int rg = w >> 1, jg = w & 1;
    const int ibase = rg * 32, jcol = jg * 32;
    const int krow = tid >> 3, kch = tid & 7;

    auto issue_tile = [&](int jb) {
        const int j0 = jb * 64;
        uint32_t base = su(KVb + (jb % 6) * 2304);
        cpasync16(base + (uint32_t)(krow * 36 + kch * 4) * 4,
                  Kg + (size_t)krow * NTOK + j0 + kch * 8);
        cpasync16(base + (uint32_t)(1152 + krow * 36 + kch * 4) * 4,
                  Vg + (size_t)krow * NTOK + j0 + kch * 8);
        asm volatile("cp.async.commit_group;");
    };

    // prologue: 4 tiles in flight + Q copy
    issue_tile(0);
    issue_tile(1);
#pragma unroll
    for (int it = 0; it < 2; it++) {
        int idx = tid + it * 256;
        int d = idx >> 4, c = idx & 15;
        uint4 v = *(const uint4*)(Qg + (size_t)d * NTOK + i0 + c * 8);
        *(uint4*)&Qs[d * 68 + c * 4] = v;
    }
    issue_tile(2);
    issue_tile(3);
    __syncthreads();

    // Q A-fragments (reused all 36 tiles)
    uint32_t qf[2][2][4];
#pragma unroll
    for (int mt = 0; mt < 2; mt++)
#pragma unroll
        for (int ks = 0; ks < 2; ks++) {
            uint32_t addrh = (uint32_t)((ks * 16 + (lane >> 4) * 8 + (lane & 7)) * 136
                                      + (ibase + mt * 16 + ((lane >> 3) & 1) * 8));
            ldsm_x4t(qf[mt][ks][0], qf[mt][ks][1], qf[mt][ks][2], qf[mt][ks][3],
                     su(Qs) + addrh * 2);
        }

    float oacc[2][4][4];
#pragma unroll
    for (int dvt = 0; dvt < 2; dvt++)
#pragma unroll
        for (int it = 0; it < 4; it++)
#pragma unroll
            for (int r = 0; r < 4; r++) oacc[dvt][it][r] = 0.f;
    float lsum[4] = {0.f, 0.f, 0.f, 0.f};
    const uint32_t zz[2] = {0u, 0u};

    auto compute_tile = [&](int jb) {
        const uint32_t* Ks = KVb + (jb % 6) * 2304;
        const uint32_t* Vs = Ks + 1152;

        // K B-fragments (trans)
        uint32_t kfr[2][4][2];
#pragma unroll
        for (int ks = 0; ks < 2; ks++)
#pragma unroll
            for (int np = 0; np < 2; np++) {
                uint32_t addrh = (uint32_t)((ks * 16 + ((lane >> 3) & 1) * 8 + (lane & 7)) * 72
                                          + (jcol + np * 16 + (lane >> 4) * 8));
                ldsm_x4t(kfr[ks][2 * np][0], kfr[ks][2 * np][1],
                         kfr[ks][2 * np + 1][0], kfr[ks][2 * np + 1][1],
                         su(Ks) + addrh * 2);
            }

        // S = Q K^T in fp16 accum
        uint32_t sc[2][4][2];
#pragma unroll
        for (int jt = 0; jt < 4; jt++) {
            mma_f16h(sc[0][jt], qf[0][0], kfr[0][jt], zz);
            mma_f16h(sc[1][jt], qf[1][0], kfr[0][jt], zz);
        }
#pragma unroll
        for (int jt = 0; jt < 4; jt++) {
            mma_f16h(sc[0][jt], qf[0][1], kfr[1][jt], sc[0][jt]);
            mma_f16h(sc[1][jt], qf[1][1], kfr[1][jt], sc[1][jt]);
        }

        // V A-fragments (non-trans) — LDS latency hides under exp
        uint32_t va[2][2][4];
#pragma unroll
        for (int dvt = 0; dvt < 2; dvt++)
#pragma unroll
            for (int kk = 0; kk < 2; kk++) {
                uint32_t addrh = (uint32_t)((dvt * 16 + ((lane >> 3) & 1) * 8 + (lane & 7)) * 72
                                          + (jcol + kk * 16 + (lane >> 4) * 8));
                ldsm_x4(va[dvt][kk][0], va[dvt][kk][1], va[dvt][kk][2], va[dvt][kk][3],
                        su(Vs) + addrh * 2);
            }

        // P^T = 2^S : ex2.f16x2 directly on accumulator regs
        uint32_t pb[2][4][2];
#pragma unroll
        for (int kk = 0; kk < 2; kk++)
#pragma unroll
            for (int mt = 0; mt < 2; mt++) {
                pb[kk][2 * mt][0]     = ex2h2(sc[mt][2 * kk][0]);
                pb[kk][2 * mt][1]     = ex2h2(sc[mt][2 * kk + 1][0]);
                pb[kk][2 * mt + 1][0] = ex2h2(sc[mt][2 * kk][1]);
                pb[kk][2 * mt + 1][1] = ex2h2(sc[mt][2 * kk + 1][1]);
            }

        // Row sums on the FMA pipe
#pragma unroll
        for (int it = 0; it < 4; it++) {
            uint32_t hs = hadd2(hadd2(pb[0][it][0], pb[0][it][1]),
                                hadd2(pb[1][it][0], pb[1][it][1]));
            lsum[it] += h2sum(hs);
        }

        // O^T += V P^T (fp32 accum)
#pragma unroll
        for (int kk = 0; kk < 2; kk++)
#pragma unroll
            for (int it = 0; it < 4; it++) {
                mma_f16(oacc[0][it], va[0][kk], pb[kk][it]);
                mma_f16(oacc[1][it], va[1][kk], pb[kk][it]);
            }
    };

    // pair loop: one barrier per TWO tiles, ring distance 4 on 6 buffers
    for (int jb = 0; jb < 36; jb += 2) {
        if (jb < 34) cpwait<2>();
        else         cpwait<0>();
        __syncthreads();
        if (jb + 4 < 36) issue_tile(jb + 4);
        if (jb + 5 < 36) issue_tile(jb + 5);
        compute_tile(jb);
        compute_tile(jb + 1);
    }

    // Quad-reduce row sums over t
#pragma unroll
    for (int it = 0; it < 4; it++) {
        lsum[it] += __shfl_xor_sync(0xffffffffu, lsum[it], 1);
        lsum[it] += __shfl_xor_sync(0xffffffffu, lsum[it], 2);
    }

    // Cross-jg reduction
    __syncthreads();
    if (t == 0) {
#pragma unroll
        for (int it = 0; it < 4; it++)
            redL[jg][rg][it * 8 + g] = lsum[it];
    }
    if (jg == 1) {
#pragma unroll
        for (int dvt = 0; dvt < 2; dvt++)
#pragma unroll
            for (int it = 0; it < 4; it++) {
                int dv = dvt * 16 + g, ii = it * 8 + 2 * t;
                redO[rg][dv][ii]         = oacc[dvt][it][0];
                redO[rg][dv][ii + 1]     = oacc[dvt][it][1];
                redO[rg][dv + 8][ii]     = oacc[dvt][it][2];
                redO[rg][dv + 8][ii + 1] = oacc[dvt][it][3];
            }
    }
    __syncthreads();
    if (jg == 0) {
        uint16_t* Ob = oh + ((size_t)b * 256 + h * 32) * NTOK;
#pragma unroll
        for (int it = 0; it < 4; it++) {
            int ii = it * 8 + 2 * t;
            float inv0 = 1.f / (redL[0][rg][ii] + redL[1][rg][ii]);
            float inv1 = 1.f / (redL[0][rg][ii + 1] + redL[1][rg][ii + 1]);
            int ig = i0 + ibase + ii;
#pragma unroll
            for (int dvt = 0; dvt < 2; dvt++) {
                int dv = dvt * 16 + g;
                float o0 = (oacc[dvt][it][0] + redO[rg][dv][ii]) * inv0;
                float o1 = (oacc[dvt][it][1] + redO[rg][dv][ii + 1]) * inv1;
                *(uint32_t*)&Ob[(size_t)dv * NTOK + ig] = f2h2(o0, o1);
                float o2 = (oacc[dvt][it][2] + redO[rg][dv + 8][ii]) * inv0;
                float o3 = (oacc[dvt][it][3] + redO[rg][dv + 8][ii + 1]) * inv1;
                *(uint32_t*)&Ob[(size_t)(dv + 8) * NTOK + ig] = f2h2(o2, o3);
            }
        }
    }
}

// ---------------------------------------------------------------------------

extern "C" void kernel_launch(void* const* d_in, const int* in_sizes, int n_in,
                              void* d_out, int out_size)
{
    const float* x     = (const float*)d_in[0];  // (4,256,48,48)
    const float* w_qkv = (const float*)d_in[1];  // (768,256)
    const float* w_out = (const float*)d_in[2];  // (256,256)
    const float* b_out = (const float*)d_in[3];  // (256)
    float* out = (float*)d_out;                  // (4,256,48,48)

    uint4 *wqkvF = nullptr, *woutF = nullptr, *qkvH = nullptr, *attnH = nullptr;
    cudaGetSymbolAddress((void**)&wqkvF, g_wqkv_frag);
    cudaGetSymbolAddress((void**)&woutF, g_wout_frag);
    cudaGetSymbolAddress((void**)&qkvH, g_qkv_h);
    cudaGetSymbolAddress((void**)&attnH, g_attn_h);

    const float qscale = 0.25507607192159975f;  // log2(e)/sqrt(32)
    const int attn_smem = 20480 * 4;            // 81920 B
    const int g3_smem = 8 * 2176 * 4;           // 69632 B

    cudaFuncSetAttribute(attn_kernel, cudaFuncAttributeMaxDynamicSharedMemorySize,
                         attn_smem);
    cudaFuncSetAttribute(gemm_f16b_kernel, cudaFuncAttributeMaxDynamicSharedMemorySize,
                         g3_smem);

    // 0) weight prep
    prep_frag_kernel<<<128, 256>>>(w_qkv, w_out, wqkvF, woutF, qscale);

    // 1) QKV projection (fp32 x -> fp16 qkv)  (864 CTAs)
    gemm_f32b_kernel<<<dim3(18, 12, 4), 256>>>(wqkvF, x, (uint16_t*)qkvH, NTOK, 256);
    // 2) Flash attention -> fp16 attn  (576 CTAs)
    attn_kernel<<<dim3(18, 32), 256, attn_smem>>>((const uint16_t*)qkvH, (uint16_t*)attnH);
    // 3) Output projection + bias -> fp32 out  (288 CTAs)
    gemm_f16b_kernel<<<dim3(18, 4, 4), 256, g3_smem>>>(woutF, (const uint16_t*)attnH,
                                                       out, b_out, NTOK);
}

// round 14
// speedup vs baseline: 1.0728x; 1.0326x over previous
#include <cuda_runtime.h>
#include <cstdint>

#define NTOK 2304

// ---------------------------------------------------------------------------
// Scratch (device globals — no allocation allowed)
// ---------------------------------------------------------------------------
__device__ uint4 g_wqkv_frag[48 * 16 * 32];            // 768x256 fp16 A-fragments
__device__ uint4 g_wout_frag[16 * 16 * 32];            // 256x256 fp16 A-fragments
__device__ uint4 g_qkv_h[(4u * 768u * NTOK) / 8];      // qkv fp16 [b][768][2304]
__device__ uint4 g_attn_h[(4u * 256u * NTOK) / 8];     // attn out fp16 [b][256][2304]

// ---------------------------------------------------------------------------
__device__ __forceinline__ uint32_t f2h2(float lo, float hi) {
    uint32_t r;
    asm("cvt.rn.f16x2.f32 %0, %1, %2;" : "=r"(r) : "f"(hi), "f"(lo));
    return r;
}
__device__ __forceinline__ uint32_t ex2h2(uint32_t x) {
    uint32_t y;
    asm("ex2.approx.f16x2 %0, %1;" : "=r"(y) : "r"(x));
    return y;
}
__device__ __forceinline__ uint32_t hadd2(uint32_t a, uint32_t b) {
    uint32_t r;
    asm("add.rn.f16x2 %0, %1, %2;" : "=r"(r) : "r"(a), "r"(b));
    return r;
}
__device__ __forceinline__ float h2sum(uint32_t h) {
    float lo, hi;
    asm("{.reg .b16 l, u;\n mov.b32 {l, u}, %2;\n cvt.f32.f16 %0, l;\n cvt.f32.f16 %1, u;}"
        : "=f"(lo), "=f"(hi) : "r"(h));
    return lo + hi;
}
__device__ __forceinline__ uint32_t su(const void* p) {
    return (uint32_t)__cvta_generic_to_shared(p);
}
__device__ __forceinline__ void cpasync16(uint32_t saddr, const void* gp) {
    asm volatile("cp.async.cg.shared.global [%0], [%1], 16;" :: "r"(saddr), "l"(gp));
}
template<int N> __device__ __forceinline__ void cpwait() {
    asm volatile("cp.async.wait_group %0;" :: "n"(N) : "memory");
}
__device__ __forceinline__ void ldsm_x4(uint32_t& r0, uint32_t& r1, uint32_t& r2,
                                        uint32_t& r3, uint32_t addr) {
    asm volatile("ldmatrix.sync.aligned.m8n8.x4.shared.b16 {%0,%1,%2,%3}, [%4];"
                 : "=r"(r0), "=r"(r1), "=r"(r2), "=r"(r3) : "r"(addr));
}
__device__ __forceinline__ void ldsm_x4t(uint32_t& r0, uint32_t& r1, uint32_t& r2,
                                         uint32_t& r3, uint32_t addr) {
    asm volatile("ldmatrix.sync.aligned.m8n8.x4.trans.shared.b16 {%0,%1,%2,%3}, [%4];"
                 : "=r"(r0), "=r"(r1), "=r"(r2), "=r"(r3) : "r"(addr));
}
__device__ __forceinline__ void mma_f16(float* c, const uint32_t* a, const uint32_t* b) {
    asm volatile(
        "mma.sync.aligned.m16n8k16.row.col.f32.f16.f16.f32 "
        "{%0,%1,%2,%3}, {%4,%5,%6,%7}, {%8,%9}, {%0,%1,%2,%3};\n"
        : "+f"(c[0]), "+f"(c[1]), "+f"(c[2]), "+f"(c[3])
        : "r"(a[0]), "r"(a[1]), "r"(a[2]), "r"(a[3]), "r"(b[0]), "r"(b[1]));
}

// ---------------------------------------------------------------------------
// Prep (fused): fp32 W -> fp16 m16n8k16 A-fragments for both weights.
// ---------------------------------------------------------------------------
__global__ void prep_frag_kernel(const float* __restrict__ Wq, const float* __restrict__ Wo,
                                 uint4* __restrict__ outq, uint4* __restrict__ outo,
                                 float qscale)
{
    int i = blockIdx.x * 256 + threadIdx.x;
    int lane = i & 31, fj = i >> 5;
    int g = lane >> 2, t = lane & 3;

    const float* W;
    uint4* dst;
    int mi, kj, oidx;
    float s0 = 1.f, s1 = 1.f;
    if (fj < 768) {
        W = Wq; dst = outq; oidx = i;
        mi = fj >> 4; kj = fj & 15;
        int r0 = mi * 16 + g;
        if (r0 < 256) s0 = qscale;
        if (r0 + 8 < 256) s1 = qscale;
    } else {
        W = Wo; dst = outo;
        int fj2 = fj - 768;
        oidx = fj2 * 32 + lane;
        mi = fj2 >> 4; kj = fj2 & 15;
    }
    int r0 = mi * 16 + g, r1 = r0 + 8;
    int c0 = kj * 16 + 2 * t, c1 = c0 + 8;
    const float* w0 = W + (size_t)r0 * 256;
    const float* w1 = W + (size_t)r1 * 256;
    uint4 o;
    o.x = f2h2(w0[c0] * s0, w0[c0 + 1] * s0);
    o.y = f2h2(w1[c0] * s1, w1[c0 + 1] * s1);
    o.z = f2h2(w0[c1] * s0, w0[c1 + 1] * s0);
    o.w = f2h2(w1[c1] * s1, w1[c1 + 1] * s1);
    dst[oidx] = o;
}

// ---------------------------------------------------------------------------
// GEMM 1: C[z] (fp16) = W (fp16 A-frags) @ B[z] (KxN fp32). BM=64, BN=128,
// BK=32. Register-staged fp32 loads, f2h2 at STS, 2-buffer, 1 sync per kb.
// ---------------------------------------------------------------------------
__global__ void __launch_bounds__(256, 2) gemm_f32b_kernel(
    const uint4* __restrict__ Afrag, const float* __restrict__ Bf_all,
    uint16_t* __restrict__ Ch_all, int N, int K)
{
    __shared__ uint32_t Bs[2][32 * 68];

    const int Kt = K >> 4, KB = K >> 5;
    const int M = 64 * gridDim.y;
    const int m0 = blockIdx.y * 64, n0 = blockIdx.x * 128, z = blockIdx.z;
    const int tid = threadIdx.x, w = tid >> 5, lane = tid & 31, g = lane >> 2, t = lane & 3;
    const int wm = (w >> 2) * 32, wn = (w & 3) * 32;
    const int miBase = (m0 + wm) >> 4;

    const float* Bf = Bf_all + (size_t)z * K * N;

    float acc[2][4][4];
#pragma unroll
    for (int mt = 0; mt < 2; mt++)
#pragma unroll
        for (int nt = 0; nt < 4; nt++)
#pragma unroll
            for (int r = 0; r < 4; r++) acc[mt][nt][r] = 0.f;

    float4 sf[4];
#pragma unroll
    for (int it = 0; it < 4; it++) {
        int r = (tid >> 5) + it * 8;
        sf[it] = *(const float4*)(Bf + (size_t)r * N + n0 + lane * 4);
    }

    for (int kb = 0; kb < KB; kb++) {
        const int cur = kb & 1;
#pragma unroll
        for (int it = 0; it < 4; it++) {
            int r = (tid >> 5) + it * 8;
            *(uint2*)&Bs[cur][r * 68 + lane * 2] =
                make_uint2(f2h2(sf[it].x, sf[it].y), f2h2(sf[it].z, sf[it].w));
        }
        __syncthreads();

        if (kb + 1 < KB) {
            const float* Bn = Bf + (size_t)((kb + 1) * 32) * N;
#pragma unroll
            for (int it = 0; it < 4; it++) {
                int r = (tid >> 5) + it * 8;
                sf[it] = *(const float4*)(Bn + (size_t)r * N + n0 + lane * 4);
            }
        }

        uint4 af[2][2];
#pragma unroll
        for (int mt = 0; mt < 2; mt++)
#pragma unroll
            for (int ks = 0; ks < 2; ks++)
                af[mt][ks] = Afrag[((size_t)(miBase + mt) * Kt + kb * 2 + ks) * 32 + lane];

#pragma unroll
        for (int ks = 0; ks < 2; ks++) {
            uint32_t bf[4][2];
#pragma unroll
            for (int np = 0; np < 2; np++) {
                uint32_t addrh = (uint32_t)((ks * 16 + ((lane >> 3) & 1) * 8 + (lane & 7)) * 136
                                          + (wn + np * 16 + (lane >> 4) * 8));
                ldsm_x4t(bf[2 * np][0], bf[2 * np][1], bf[2 * np + 1][0], bf[2 * np + 1][1],
                         su(&Bs[cur][0]) + addrh * 2);
            }
#pragma unroll
            for (int mt = 0; mt < 2; mt++)
#pragma unroll
                for (int nt = 0; nt < 4; nt++)
                    mma_f16(acc[mt][nt], (const uint32_t*)&af[mt][ks], bf[nt]);
        }
    }

    uint16_t* Ch = Ch_all + (size_t)z * M * N;
#pragma unroll
    for (int mt = 0; mt < 2; mt++) {
        int ra = m0 + wm + mt * 16 + g;
#pragma unroll
        for (int nt = 0; nt < 4; nt++) {
            int col = n0 + wn + nt * 8 + 2 * t;
            *(uint32_t*)&Ch[(size_t)ra * N + col] = f2h2(acc[mt][nt][0], acc[mt][nt][1]);
            *(uint32_t*)&Ch[(size_t)(ra + 8) * N + col] = f2h2(acc[mt][nt][2], acc[mt][nt][3]);
        }
    }
}

// ---------------------------------------------------------------------------
// GEMM 3: C[z] (fp32, +bias) = W (fp16 A-frags) @ B[z] (KxN fp16). K=256.
// ALL 8 K-stages resident in smem (measured 9.95us).
// ---------------------------------------------------------------------------
__global__ void __launch_bounds__(256, 2) gemm_f16b_kernel(
    const uint4* __restrict__ Afrag, const uint16_t* __restrict__ Bh_all,
    float* __restrict__ Cf_all, const float* __restrict__ bias, int N)
{
    extern __shared__ uint32_t Bsd[];  // [8][32*68]

    const int K = 256, Kt = 16;
    const int M = 64 * gridDim.y;
    const int m0 = blockIdx.y * 64, n0 = blockIdx.x * 128, z = blockIdx.z;
    const int tid = threadIdx.x, w = tid >> 5, lane = tid & 31, g = lane >> 2, t = lane & 3;
    const int wm = (w >> 2) * 32, wn = (w & 3) * 32;
    const int miBase = (m0 + wm) >> 4;

    const uint16_t* Bh = Bh_all + (size_t)z * K * N;

    float acc[2][4][4];
#pragma unroll
    for (int mt = 0; mt < 2; mt++)
#pragma unroll
        for (int nt = 0; nt < 4; nt++)
#pragma unroll
            for (int r = 0; r < 4; r++) acc[mt][nt][r] = 0.f;

#pragma unroll
    for (int kb = 0; kb < 8; kb++) {
#pragma unroll
        for (int it = 0; it < 2; it++) {
            int idx = tid + it * 256;
            int r = idx >> 4, c16 = idx & 15;
            cpasync16(su(&Bsd[kb * 2176 + r * 68 + c16 * 4]),
                      Bh + (size_t)(kb * 32 + r) * N + n0 + c16 * 8);
        }
        asm volatile("cp.async.commit_group;");
    }

    uint4 afA[2][2], afB[2][2];
#pragma unroll
    for (int mt = 0; mt < 2; mt++)
#pragma unroll
        for (int ks = 0; ks < 2; ks++)
            afA[mt][ks] = Afrag[((size_t)(miBase + mt) * Kt + ks) * 32 + lane];

#pragma unroll
    for (int kb = 0; kb < 8; kb++) {
        if      (kb == 0) cpwait<7>();
        else if (kb == 1) cpwait<6>();
        else if (kb == 2) cpwait<5>();
        else if (kb == 3) cpwait<4>();
        else if (kb == 4) cpwait<3>();
        else if (kb == 5) cpwait<2>();
        else if (kb == 6) cpwait<1>();
        else              cpwait<0>();
        __syncthreads();

        if (kb + 1 < 8) {
#pragma unroll
            for (int mt = 0; mt < 2; mt++)
#pragma unroll
                for (int ks = 0; ks < 2; ks++)
                    afB[mt][ks] = Afrag[((size_t)(miBase + mt) * Kt + (kb + 1) * 2 + ks) * 32 + lane];
        }

#pragma unroll
        for (int ks = 0; ks < 2; ks++) {
            uint32_t bf[4][2];
#pragma unroll
            for (int np = 0; np < 2; np++) {
                uint32_t addrh = (uint32_t)((ks * 16 + ((lane >> 3) & 1) * 8 + (lane & 7)) * 136
                                          + (wn + np * 16 + (lane >> 4) * 8));
                ldsm_x4t(bf[2 * np][0], bf[2 * np][1], bf[2 * np + 1][0], bf[2 * np + 1][1],
                         su(&Bsd[kb * 2176]) + addrh * 2);
            }
#pragma unroll
            for (int mt = 0; mt < 2; mt++)
#pragma unroll
                for (int nt = 0; nt < 4; nt++)
                    mma_f16(acc[mt][nt], (const uint32_t*)&afA[mt][ks], bf[nt]);
        }
#pragma unroll
        for (int mt = 0; mt < 2; mt++)
#pragma unroll
            for (int ks = 0; ks < 2; ks++)
                afA[mt][ks] = afB[mt][ks];
    }

    float* Cf = Cf_all + (size_t)z * M * N;
#pragma unroll
    for (int mt = 0; mt < 2; mt++) {
        int ra = m0 + wm + mt * 16 + g;
        float ba = bias[ra], bb = bias[ra + 8];
#pragma unroll
        for (int nt = 0; nt < 4; nt++) {
            int col = n0 + wn + nt * 8 + 2 * t;
            *(float2*)(Cf + (size_t)ra * N + col) =
                make_float2(acc[mt][nt][0] + ba, acc[mt][nt][1] + ba);
            *(float2*)(Cf + (size_t)(ra + 8) * N + col) =
                make_float2(acc[mt][nt][2] + bb, acc[mt][nt][3] + bb);
        }
    }
}

// ---------------------------------------------------------------------------
// Flash attention (r7 body — best measured total). Per CTA: (b,h) x 128
// q-rows. 8 warps: jg=w&1 (j-half, Bc=64), rg=w>>1 (32 q-rows). QK fp16 mma
// with fp32 accum; PV fp16 (P C-frag packs directly via f2h2 + ex2.f16x2);
// row sums via HADD2 on the FMA pipe. cp.async double-buffered KV, one
// syncthreads per tile.
// ---------------------------------------------------------------------------
__global__ void __launch_bounds__(256, 2) attn_kernel(const uint16_t* __restrict__ qkvh,
                                                      uint16_t* __restrict__ oh)
{
    __shared__ uint32_t Qs[32 * 68];          // [d][i]  pitch 136 halves
    __shared__ uint32_t KVs[2][2][32 * 36];   // [buf][K/V][d][j] pitch 72 halves
    __shared__ float redO[4][32][33];
    __shared__ float redL[2][4][32];

    const int bh = blockIdx.y, b = bh >> 3, h = bh & 7;
    const int i0 = blockIdx.x * 128;
    const uint16_t* Qg = qkvh + ((size_t)b * 768 + h * 32) * NTOK;
    const uint16_t* Kg = Qg + (size_t)256 * NTOK;
    const uint16_t* Vg = Qg + (size_t)512 * NTOK;
    const int tid = threadIdx.x, w = tid >> 5, lane = tid & 31, g = lane >> 2, t = lane & 3;
    const int rg = w >> 1, jg = w & 1;
    const int ibase = rg * 32, jcol = jg * 32;

    const int krow = tid >> 3, kch = tid & 7;

    // prefetch K/V tile 0
    cpasync16(su(&KVs[0][0][krow * 36 + kch * 4]), Kg + (size_t)krow * NTOK + kch * 8);
    cpasync16(su(&KVs[0][1][krow * 36 + kch * 4]), Vg + (size_t)krow * NTOK + kch * 8);
    asm volatile("cp.async.commit_group;");

    // Q tile -> smem
#pragma unroll
    for (int it = 0; it < 2; it++) {
        int idx = tid + it * 256;
        int d = idx >> 4, c = idx & 15;
        uint4 v = *(const uint4*)(Qg + (size_t)d * NTOK + i0 + c * 8);
        *(uint4*)&Qs[d * 68 + c * 4] = v;
    }
    __syncthreads();

    // Q A-fragments (reused all 36 tiles)
    uint32_t qf[2][2][4];
#pragma unroll
    for (int mt = 0; mt < 2; mt++)
#pragma unroll
        for (int ks = 0; ks < 2; ks++) {
            uint32_t addrh = (uint32_t)((ks * 16 + (lane >> 4) * 8 + (lane & 7)) * 136
                                      + (ibase + mt * 16 + ((lane >> 3) & 1) * 8));
            ldsm_x4t(qf[mt][ks][0], qf[mt][ks][1], qf[mt][ks][2], qf[mt][ks][3],
                     su(Qs) + addrh * 2);
        }

    float oacc[2][4][4];
#pragma unroll
    for (int dvt = 0; dvt < 2; dvt++)
#pragma unroll
        for (int it = 0; it < 4; it++)
#pragma unroll
            for (int r = 0; r < 4; r++) oacc[dvt][it][r] = 0.f;
    float lsum[4] = {0.f, 0.f, 0.f, 0.f};

    for (int jb = 0; jb < 36; jb++) {
        const int cur = jb & 1;
        cpwait<0>();
        __syncthreads();

        if (jb + 1 < 36) {
            const int j0 = (jb + 1) * 64;
            cpasync16(su(&KVs[cur ^ 1][0][krow * 36 + kch * 4]),
                      Kg + (size_t)krow * NTOK + j0 + kch * 8);
            cpasync16(su(&KVs[cur ^ 1][1][krow * 36 + kch * 4]),
                      Vg + (size_t)krow * NTOK + j0 + kch * 8);
            asm volatile("cp.async.commit_group;");
        }

        const uint32_t* Ks = KVs[cur][0];
        const uint32_t* Vs = KVs[cur][1];

        // K B-fragments (trans)
        uint32_t kfr[2][4][2];
#pragma unroll
        for (int ks = 0; ks < 2; ks++)
#pragma unroll
            for (int np = 0; np < 2; np++) {
                uint32_t addrh = (uint32_t)((ks * 16 + ((lane >> 3) & 1) * 8 + (lane & 7)) * 72
                                          + (jcol + np * 16 + (lane >> 4) * 8));
                ldsm_x4t(kfr[ks][2 * np][0], kfr[ks][2 * np][1],
                         kfr[ks][2 * np + 1][0], kfr[ks][2 * np + 1][1],
                         su(Ks) + addrh * 2);
            }

        // S = Q K^T (fp32 accum)
        float s[2][4][4] = {};
#pragma unroll
        for (int ks = 0; ks < 2; ks++)
#pragma unroll
            for (int jt = 0; jt < 4; jt++) {
                mma_f16(s[0][jt], qf[0][ks], kfr[ks][jt]);
                mma_f16(s[1][jt], qf[1][ks], kfr[ks][jt]);
            }

        // V A-fragments (non-trans) — LDS latency hides under exp
        uint32_t va[2][2][4];
#pragma unroll
        for (int dvt = 0; dvt < 2; dvt++)
#pragma unroll
            for (int kk = 0; kk < 2; kk++) {
                uint32_t addrh = (uint32_t)((dvt * 16 + ((lane >> 3) & 1) * 8 + (lane & 7)) * 72
                                          + (jcol + kk * 16 + (lane >> 4) * 8));
                ldsm_x4(va[dvt][kk][0], va[dvt][kk][1], va[dvt][kk][2], va[dvt][kk][3],
                        su(Vs) + addrh * 2);
            }

        // P^T B-fragments: pack + f16x2 exp (no max subtraction)
        uint32_t pb[2][4][2];
#pragma unroll
        for (int kk = 0; kk < 2; kk++)
#pragma unroll
            for (int mt = 0; mt < 2; mt++) {
                pb[kk][2 * mt][0]     = ex2h2(f2h2(s[mt][2 * kk][0],     s[mt][2 * kk][1]));
                pb[kk][2 * mt][1]     = ex2h2(f2h2(s[mt][2 * kk + 1][0], s[mt][2 * kk + 1][1]));
                pb[kk][2 * mt + 1][0] = ex2h2(f2h2(s[mt][2 * kk][2],     s[mt][2 * kk][3]));
                pb[kk][2 * mt + 1][1] = ex2h2(f2h2(s[mt][2 * kk + 1][2], s[mt][2 * kk + 1][3]));
            }

        // Row sums on the FMA pipe
#pragma unroll
        for (int it = 0; it < 4; it++) {
            uint32_t hs = hadd2(hadd2(pb[0][it][0], pb[0][it][1]),
                                hadd2(pb[1][it][0], pb[1][it][1]));
            lsum[it] += h2sum(hs);
        }

        // O^T += V P^T (fp32 accum)
#pragma unroll
        for (int kk = 0; kk < 2; kk++)
#pragma unroll
            for (int it = 0; it < 4; it++) {
                mma_f16(oacc[0][it], va[0][kk], pb[kk][it]);
                mma_f16(oacc[1][it], va[1][kk], pb[kk][it]);
            }
    }

    // Quad-reduce row sums over t
#pragma unroll
    for (int it = 0; it < 4; it++) {
        lsum[it] += __shfl_xor_sync(0xffffffffu, lsum[it], 1);
        lsum[it] += __shfl_xor_sync(0xffffffffu, lsum[it], 2);
    }

    // Cross-jg reduction
    __syncthreads();
    if (t == 0) {
#pragma unroll
        for (int it = 0; it < 4; it++)
            redL[jg][rg][it * 8 + g] = lsum[it];
    }
    if (jg == 1) {
#pragma unroll
        for (int dvt = 0; dvt < 2; dvt++)
#pragma unroll
            for (int it = 0; it < 4; it++) {
                int dv = dvt * 16 + g, ii = it * 8 + 2 * t;
                redO[rg][dv][ii]         = oacc[dvt][it][0];
                redO[rg][dv][ii + 1]     = oacc[dvt][it][1];
                redO[rg][dv + 8][ii]     = oacc[dvt][it][2];
                redO[rg][dv + 8][ii + 1] = oacc[dvt][it][3];
            }
    }
    __syncthreads();
    if (jg == 0) {
        uint16_t* Ob = oh + ((size_t)b * 256 + h * 32) * NTOK;
#pragma unroll
        for (int it = 0; it < 4; it++) {
            int ii = it * 8 + 2 * t;
            float inv0 = 1.f / (redL[0][rg][ii] + redL[1][rg][ii]);
            float inv1 = 1.f / (redL[0][rg][ii + 1] + redL[1][rg][ii + 1]);
            int ig = i0 + ibase + ii;
#pragma unroll
            for (int dvt = 0; dvt < 2; dvt++) {
                int dv = dvt * 16 + g;
                float o0 = (oacc[dvt][it][0] + redO[rg][dv][ii]) * inv0;
                float o1 = (oacc[dvt][it][1] + redO[rg][dv][ii + 1]) * inv1;
                *(uint32_t*)&Ob[(size_t)dv * NTOK + ig] = f2h2(o0, o1);
                float o2 = (oacc[dvt][it][2] + redO[rg][dv + 8][ii]) * inv0;
                float o3 = (oacc[dvt][it][3] + redO[rg][dv + 8][ii + 1]) * inv1;
                *(uint32_t*)&Ob[(size_t)(dv + 8) * NTOK + ig] = f2h2(o2, o3);
            }
        }
    }
}

// ---------------------------------------------------------------------------

extern "C" void kernel_launch(void* const* d_in, const int* in_sizes, int n_in,
                              void* d_out, int out_size)
{
    const float* x     = (const float*)d_in[0];  // (4,256,48,48)
    const float* w_qkv = (const float*)d_in[1];  // (768,256)
    const float* w_out = (const float*)d_in[2];  // (256,256)
    const float* b_out = (const float*)d_in[3];  // (256)
    float* out = (float*)d_out;                  // (4,256,48,48)

    uint4 *wqkvF = nullptr, *woutF = nullptr, *qkvH = nullptr, *attnH = nullptr;
    cudaGetSymbolAddress((void**)&wqkvF, g_wqkv_frag);
    cudaGetSymbolAddress((void**)&woutF, g_wout_frag);
    cudaGetSymbolAddress((void**)&qkvH, g_qkv_h);
    cudaGetSymbolAddress((void**)&attnH, g_attn_h);

    const float qscale = 0.25507607192159975f;  // log2(e)/sqrt(32)
    const int g3_smem = 8 * 2176 * 4;           // 69632 B

    cudaFuncSetAttribute(gemm_f16b_kernel, cudaFuncAttributeMaxDynamicSharedMemorySize,
                         g3_smem);

    // 0) weight prep (fused)
    prep_frag_kernel<<<128, 256>>>(w_qkv, w_out, wqkvF, woutF, qscale);

    // 1) QKV projection (fp32 x -> fp16 qkv)  (864 CTAs)
    gemm_f32b_kernel<<<dim3(18, 12, 4), 256>>>(wqkvF, x, (uint16_t*)qkvH, NTOK, 256);
    // 2) Flash attention -> fp16 attn  (576 CTAs)
    attn_kernel<<<dim3(18, 32), 256>>>((const uint16_t*)qkvH, (uint16_t*)attnH);
    // 3) Output projection + bias -> fp32 out  (288 CTAs)
    gemm_f16b_kernel<<<dim3(18, 4, 4), 256, g3_smem>>>(woutF, (const uint16_t*)attnH,
                                                       out, b_out, NTOK);
}

// round 15
// speedup vs baseline: 1.0797x; 1.0064x over previous
#include <cuda_runtime.h>
#include <cstdint>

#define NTOK 2304

// ---------------------------------------------------------------------------
// Scratch (device globals — no allocation allowed)
// ---------------------------------------------------------------------------
__device__ uint4 g_wqkv_frag[48 * 16 * 32];            // 768x256 fp16 A-fragments
__device__ uint4 g_wout_frag[16 * 16 * 32];            // 256x256 fp16 A-fragments
__device__ uint4 g_qkv_h[(4u * 768u * NTOK) / 8];      // qkv fp16 [b][768][2304]
__device__ uint4 g_attn_h[(4u * 256u * NTOK) / 8];     // attn out fp16 [b][256][2304]

// ---------------------------------------------------------------------------
__device__ __forceinline__ uint32_t f2h2(float lo, float hi) {
    uint32_t r;
    asm("cvt.rn.f16x2.f32 %0, %1, %2;" : "=r"(r) : "f"(hi), "f"(lo));
    return r;
}
__device__ __forceinline__ uint32_t ex2h2(uint32_t x) {
    uint32_t y;
    asm("ex2.approx.f16x2 %0, %1;" : "=r"(y) : "r"(x));
    return y;
}
__device__ __forceinline__ uint32_t hadd2(uint32_t a, uint32_t b) {
    uint32_t r;
    asm("add.rn.f16x2 %0, %1, %2;" : "=r"(r) : "r"(a), "r"(b));
    return r;
}
__device__ __forceinline__ float h2sum(uint32_t h) {
    float lo, hi;
    asm("{.reg .b16 l, u;\n mov.b32 {l, u}, %2;\n cvt.f32.f16 %0, l;\n cvt.f32.f16 %1, u;}"
        : "=f"(lo), "=f"(hi) : "r"(h));
    return lo + hi;
}
__device__ __forceinline__ uint32_t su(const void* p) {
    return (uint32_t)__cvta_generic_to_shared(p);
}
__device__ __forceinline__ void cpasync16(uint32_t saddr, const void* gp) {
    asm volatile("cp.async.cg.shared.global [%0], [%1], 16;" :: "r"(saddr), "l"(gp));
}
template<int N> __device__ __forceinline__ void cpwait() {
    asm volatile("cp.async.wait_group %0;" :: "n"(N) : "memory");
}
__device__ __forceinline__ void ldsm_x4(uint32_t& r0, uint32_t& r1, uint32_t& r2,
                                        uint32_t& r3, uint32_t addr) {
    asm volatile("ldmatrix.sync.aligned.m8n8.x4.shared.b16 {%0,%1,%2,%3}, [%4];"
                 : "=r"(r0), "=r"(r1), "=r"(r2), "=r"(r3) : "r"(addr));
}
__device__ __forceinline__ void ldsm_x4t(uint32_t& r0, uint32_t& r1, uint32_t& r2,
                                         uint32_t& r3, uint32_t addr) {
    asm volatile("ldmatrix.sync.aligned.m8n8.x4.trans.shared.b16 {%0,%1,%2,%3}, [%4];"
                 : "=r"(r0), "=r"(r1), "=r"(r2), "=r"(r3) : "r"(addr));
}
__device__ __forceinline__ void mma_f16(float* c, const uint32_t* a, const uint32_t* b) {
    asm volatile(
        "mma.sync.aligned.m16n8k16.row.col.f32.f16.f16.f32 "
        "{%0,%1,%2,%3}, {%4,%5,%6,%7}, {%8,%9}, {%0,%1,%2,%3};\n"
        : "+f"(c[0]), "+f"(c[1]), "+f"(c[2]), "+f"(c[3])
        : "r"(a[0]), "r"(a[1]), "r"(a[2]), "r"(a[3]), "r"(b[0]), "r"(b[1]));
}
__device__ __forceinline__ void mma_f16h(uint32_t* d, const uint32_t* a, const uint32_t* b,
                                         const uint32_t* c) {
    asm volatile(
        "mma.sync.aligned.m16n8k16.row.col.f16.f16.f16.f16 "
        "{%0,%1}, {%2,%3,%4,%5}, {%6,%7}, {%8,%9};\n"
        : "=r"(d[0]), "=r"(d[1])
        : "r"(a[0]), "r"(a[1]), "r"(a[2]), "r"(a[3]),
          "r"(b[0]), "r"(b[1]), "r"(c[0]), "r"(c[1]));
}

// ---------------------------------------------------------------------------
// Prep (fused): fp32 W -> fp16 m16n8k16 A-fragments for both weights.
// ---------------------------------------------------------------------------
__global__ void prep_frag_kernel(const float* __restrict__ Wq, const float* __restrict__ Wo,
                                 uint4* __restrict__ outq, uint4* __restrict__ outo,
                                 float qscale)
{
    int i = blockIdx.x * 256 + threadIdx.x;
    int lane = i & 31, fj = i >> 5;
    int g = lane >> 2, t = lane & 3;

    const float* W;
    uint4* dst;
    int mi, kj, oidx;
    float s0 = 1.f, s1 = 1.f;
    if (fj < 768) {
        W = Wq; dst = outq; oidx = i;
        mi = fj >> 4; kj = fj & 15;
        int r0 = mi * 16 + g;
        if (r0 < 256) s0 = qscale;
        if (r0 + 8 < 256) s1 = qscale;
    } else {
        W = Wo; dst = outo;
        int fj2 = fj - 768;
        oidx = fj2 * 32 + lane;
        mi = fj2 >> 4; kj = fj2 & 15;
    }
    int r0 = mi * 16 + g, r1 = r0 + 8;
    int c0 = kj * 16 + 2 * t, c1 = c0 + 8;
    const float* w0 = W + (size_t)r0 * 256;
    const float* w1 = W + (size_t)r1 * 256;
    uint4 o;
    o.x = f2h2(w0[c0] * s0, w0[c0 + 1] * s0);
    o.y = f2h2(w1[c0] * s1, w1[c0 + 1] * s1);
    o.z = f2h2(w0[c1] * s0, w0[c1 + 1] * s0);
    o.w = f2h2(w1[c1] * s1, w1[c1 + 1] * s1);
    dst[oidx] = o;
}

// ---------------------------------------------------------------------------
// GEMM 1: C[z] (fp16) = W (fp16 A-frags) @ B[z] (KxN fp32). BM=64, BN=128,
// BK=32. Register-staged fp32 loads, f2h2 at STS, 2-buffer, 1 sync per kb.
// ---------------------------------------------------------------------------
__global__ void __launch_bounds__(256, 2) gemm_f32b_kernel(
    const uint4* __restrict__ Afrag, const float* __restrict__ Bf_all,
    uint16_t* __restrict__ Ch_all, int N, int K)
{
    __shared__ uint32_t Bs[2][32 * 68];

    const int Kt = K >> 4, KB = K >> 5;
    const int M = 64 * gridDim.y;
    const int m0 = blockIdx.y * 64, n0 = blockIdx.x * 128, z = blockIdx.z;
    const int tid = threadIdx.x, w = tid >> 5, lane = tid & 31, g = lane >> 2, t = lane & 3;
    const int wm = (w >> 2) * 32, wn = (w & 3) * 32;
    const int miBase = (m0 + wm) >> 4;

    const float* Bf = Bf_all + (size_t)z * K * N;

    float acc[2][4][4];
#pragma unroll
    for (int mt = 0; mt < 2; mt++)
#pragma unroll
        for (int nt = 0; nt < 4; nt++)
#pragma unroll
            for (int r = 0; r < 4; r++) acc[mt][nt][r] = 0.f;

    float4 sf[4];
#pragma unroll
    for (int it = 0; it < 4; it++) {
        int r = (tid >> 5) + it * 8;
        sf[it] = *(const float4*)(Bf + (size_t)r * N + n0 + lane * 4);
    }

    for (int kb = 0; kb < KB; kb++) {
        const int cur = kb & 1;
#pragma unroll
        for (int it = 0; it < 4; it++) {
            int r = (tid >> 5) + it * 8;
            *(uint2*)&Bs[cur][r * 68 + lane * 2] =
                make_uint2(f2h2(sf[it].x, sf[it].y), f2h2(sf[it].z, sf[it].w));
        }
        __syncthreads();

        if (kb + 1 < KB) {
            const float* Bn = Bf + (size_t)((kb + 1) * 32) * N;
#pragma unroll
            for (int it = 0; it < 4; it++) {
                int r = (tid >> 5) + it * 8;
                sf[it] = *(const float4*)(Bn + (size_t)r * N + n0 + lane * 4);
            }
        }

        uint4 af[2][2];
#pragma unroll
        for (int mt = 0; mt < 2; mt++)
#pragma unroll
            for (int ks = 0; ks < 2; ks++)
                af[mt][ks] = Afrag[((size_t)(miBase + mt) * Kt + kb * 2 + ks) * 32 + lane];

#pragma unroll
        for (int ks = 0; ks < 2; ks++) {
            uint32_t bf[4][2];
#pragma unroll
            for (int np = 0; np < 2; np++) {
                uint32_t addrh = (uint32_t)((ks * 16 + ((lane >> 3) & 1) * 8 + (lane & 7)) * 136
                                          + (wn + np * 16 + (lane >> 4) * 8));
                ldsm_x4t(bf[2 * np][0], bf[2 * np][1], bf[2 * np + 1][0], bf[2 * np + 1][1],
                         su(&Bs[cur][0]) + addrh * 2);
            }
#pragma unroll
            for (int mt = 0; mt < 2; mt++)
#pragma unroll
                for (int nt = 0; nt < 4; nt++)
                    mma_f16(acc[mt][nt], (const uint32_t*)&af[mt][ks], bf[nt]);
        }
    }

    uint16_t* Ch = Ch_all + (size_t)z * M * N;
#pragma unroll
    for (int mt = 0; mt < 2; mt++) {
        int ra = m0 + wm + mt * 16 + g;
#pragma unroll
        for (int nt = 0; nt < 4; nt++) {
            int col = n0 + wn + nt * 8 + 2 * t;
            *(uint32_t*)&Ch[(size_t)ra * N + col] = f2h2(acc[mt][nt][0], acc[mt][nt][1]);
            *(uint32_t*)&Ch[(size_t)(ra + 8) * N + col] = f2h2(acc[mt][nt][2], acc[mt][nt][3]);
        }
    }
}

// ---------------------------------------------------------------------------
// GEMM 3: C[z] (fp32, +bias) = W (fp16 A-frags) @ B[z] (KxN fp16). K=256.
// ALL 8 K-stages resident in smem (measured 9.95us).
// ---------------------------------------------------------------------------
__global__ void __launch_bounds__(256, 2) gemm_f16b_kernel(
    const uint4* __restrict__ Afrag, const uint16_t* __restrict__ Bh_all,
    float* __restrict__ Cf_all, const float* __restrict__ bias, int N)
{
    extern __shared__ uint32_t Bsd[];  // [8][32*68]

    const int K = 256, Kt = 16;
    const int M = 64 * gridDim.y;
    const int m0 = blockIdx.y * 64, n0 = blockIdx.x * 128, z = blockIdx.z;
    const int tid = threadIdx.x, w = tid >> 5, lane = tid & 31, g = lane >> 2, t = lane & 3;
    const int wm = (w >> 2) * 32, wn = (w & 3) * 32;
    const int miBase = (m0 + wm) >> 4;

    const uint16_t* Bh = Bh_all + (size_t)z * K * N;

    float acc[2][4][4];
#pragma unroll
    for (int mt = 0; mt < 2; mt++)
#pragma unroll
        for (int nt = 0; nt < 4; nt++)
#pragma unroll
            for (int r = 0; r < 4; r++) acc[mt][nt][r] = 0.f;

#pragma unroll
    for (int kb = 0; kb < 8; kb++) {
#pragma unroll
        for (int it = 0; it < 2; it++) {
            int idx = tid + it * 256;
            int r = idx >> 4, c16 = idx & 15;
            cpasync16(su(&Bsd[kb * 2176 + r * 68 + c16 * 4]),
                      Bh + (size_t)(kb * 32 + r) * N + n0 + c16 * 8);
        }
        asm volatile("cp.async.commit_group;");
    }

    uint4 afA[2][2], afB[2][2];
#pragma unroll
    for (int mt = 0; mt < 2; mt++)
#pragma unroll
        for (int ks = 0; ks < 2; ks++)
            afA[mt][ks] = Afrag[((size_t)(miBase + mt) * Kt + ks) * 32 + lane];

#pragma unroll
    for (int kb = 0; kb < 8; kb++) {
        if      (kb == 0) cpwait<7>();
        else if (kb == 1) cpwait<6>();
        else if (kb == 2) cpwait<5>();
        else if (kb == 3) cpwait<4>();
        else if (kb == 4) cpwait<3>();
        else if (kb == 5) cpwait<2>();
        else if (kb == 6) cpwait<1>();
        else              cpwait<0>();
        __syncthreads();

        if (kb + 1 < 8) {
#pragma unroll
            for (int mt = 0; mt < 2; mt++)
#pragma unroll
                for (int ks = 0; ks < 2; ks++)
                    afB[mt][ks] = Afrag[((size_t)(miBase + mt) * Kt + (kb + 1) * 2 + ks) * 32 + lane];
        }

#pragma unroll
        for (int ks = 0; ks < 2; ks++) {
            uint32_t bf[4][2];
#pragma unroll
            for (int np = 0; np < 2; np++) {
                uint32_t addrh = (uint32_t)((ks * 16 + ((lane >> 3) & 1) * 8 + (lane & 7)) * 136
                                          + (wn + np * 16 + (lane >> 4) * 8));
                ldsm_x4t(bf[2 * np][0], bf[2 * np][1], bf[2 * np + 1][0], bf[2 * np + 1][1],
                         su(&Bsd[kb * 2176]) + addrh * 2);
            }
#pragma unroll
            for (int mt = 0; mt < 2; mt++)
#pragma unroll
                for (int nt = 0; nt < 4; nt++)
                    mma_f16(acc[mt][nt], (const uint32_t*)&afA[mt][ks], bf[nt]);
        }
#pragma unroll
        for (int mt = 0; mt < 2; mt++)
#pragma unroll
            for (int ks = 0; ks < 2; ks++)
                afA[mt][ks] = afB[mt][ks];
    }

    float* Cf = Cf_all + (size_t)z * M * N;
#pragma unroll
    for (int mt = 0; mt < 2; mt++) {
        int ra = m0 + wm + mt * 16 + g;
        float ba = bias[ra], bb = bias[ra + 8];
#pragma unroll
        for (int nt = 0; nt < 4; nt++) {
            int col = n0 + wn + nt * 8 + 2 * t;
            *(float2*)(Cf + (size_t)ra * N + col) =
                make_float2(acc[mt][nt][0] + ba, acc[mt][nt][1] + ba);
            *(float2*)(Cf + (size_t)(ra + 8) * N + col) =
                make_float2(acc[mt][nt][2] + bb, acc[mt][nt][3] + bb);
        }
    }
}

// ---------------------------------------------------------------------------
// Flash attention — r8 body (fp16-accum QK, direct ex2 on accumulators) with
// __launch_bounds__(256,3): forces <=84 regs so THREE CTAs fit per SM
// (24 warps/SM vs 16 before). Theory: attn is latency-bound (tensor pipe
// ~25% busy, 31 cyc/mma/SMSP vs 4-8 floor) and every prior variant ran the
// same 16-warp occupancy — this is the untested axis. Static smem 44KB x 3
// = 132KB fits.
// ---------------------------------------------------------------------------
__global__ void __launch_bounds__(256, 3) attn_kernel(const uint16_t* __restrict__ qkvh,
                                                      uint16_t* __restrict__ oh)
{
    __shared__ uint32_t Qs[32 * 68];          // [d][i]  pitch 136 halves
    __shared__ uint32_t KVs[2][2][32 * 36];   // [buf][K/V][d][j] pitch 72 halves
    __shared__ float redO[4][32][33];
    __shared__ float redL[2][4][32];

    const int bh = blockIdx.y, b = bh >> 3, h = bh & 7;
    const int i0 = blockIdx.x * 128;
    const uint16_t* Qg = qkvh + ((size_t)b * 768 + h * 32) * NTOK;
    const uint16_t* Kg = Qg + (size_t)256 * NTOK;
    const uint16_t* Vg = Qg + (size_t)512 * NTOK;
    const int tid = threadIdx.x, w = tid >> 5, lane = tid & 31, g = lane >> 2, t = lane & 3;
    const int rg = w >> 1, jg = w & 1;
    const int ibase = rg * 32, jcol = jg * 32;

    const int krow = tid >> 3, kch = tid & 7;

    // prefetch K/V tile 0
    cpasync16(su(&KVs[0][0][krow * 36 + kch * 4]), Kg + (size_t)krow * NTOK + kch * 8);
    cpasync16(su(&KVs[0][1][krow * 36 + kch * 4]), Vg + (size_t)krow * NTOK + kch * 8);
    asm volatile("cp.async.commit_group;");

    // Q tile -> smem
#pragma unroll
    for (int it = 0; it < 2; it++) {
        int idx = tid + it * 256;
        int d = idx >> 4, c = idx & 15;
        uint4 v = *(const uint4*)(Qg + (size_t)d * NTOK + i0 + c * 8);
        *(uint4*)&Qs[d * 68 + c * 4] = v;
    }
    __syncthreads();

    // Q A-fragments (reused all 36 tiles)
    uint32_t qf[2][2][4];
#pragma unroll
    for (int mt = 0; mt < 2; mt++)
#pragma unroll
        for (int ks = 0; ks < 2; ks++) {
            uint32_t addrh = (uint32_t)((ks * 16 + (lane >> 4) * 8 + (lane & 7)) * 136
                                      + (ibase + mt * 16 + ((lane >> 3) & 1) * 8));
            ldsm_x4t(qf[mt][ks][0], qf[mt][ks][1], qf[mt][ks][2], qf[mt][ks][3],
                     su(Qs) + addrh * 2);
        }

    float oacc[2][4][4];
#pragma unroll
    for (int dvt = 0; dvt < 2; dvt++)
#pragma unroll
        for (int it = 0; it < 4; it++)
#pragma unroll
            for (int r = 0; r < 4; r++) oacc[dvt][it][r] = 0.f;
    float lsum[4] = {0.f, 0.f, 0.f, 0.f};
    const uint32_t zz[2] = {0u, 0u};

    for (int jb = 0; jb < 36; jb++) {
        const int cur = jb & 1;
        cpwait<0>();
        __syncthreads();

        if (jb + 1 < 36) {
            const int j0 = (jb + 1) * 64;
            cpasync16(su(&KVs[cur ^ 1][0][krow * 36 + kch * 4]),
                      Kg + (size_t)krow * NTOK + j0 + kch * 8);
            cpasync16(su(&KVs[cur ^ 1][1][krow * 36 + kch * 4]),
                      Vg + (size_t)krow * NTOK + j0 + kch * 8);
            asm volatile("cp.async.commit_group;");
        }

        const uint32_t* Ks = KVs[cur][0];
        const uint32_t* Vs = KVs[cur][1];

        // K B-fragments (trans)
        uint32_t kfr[2][4][2];
#pragma unroll
        for (int ks = 0; ks < 2; ks++)
#pragma unroll
            for (int np = 0; np < 2; np++) {
                uint32_t addrh = (uint32_t)((ks * 16 + ((lane >> 3) & 1) * 8 + (lane & 7)) * 72
                                          + (jcol + np * 16 + (lane >> 4) * 8));
                ldsm_x4t(kfr[ks][2 * np][0], kfr[ks][2 * np][1],
                         kfr[ks][2 * np + 1][0], kfr[ks][2 * np + 1][1],
                         su(Ks) + addrh * 2);
            }

        // S = Q K^T in fp16 accum (16 live regs instead of 32)
        uint32_t sc[2][4][2];
#pragma unroll
        for (int jt = 0; jt < 4; jt++) {
            mma_f16h(sc[0][jt], qf[0][0], kfr[0][jt], zz);
            mma_f16h(sc[1][jt], qf[1][0], kfr[0][jt], zz);
        }
#pragma unroll
        for (int jt = 0; jt < 4; jt++) {
            mma_f16h(sc[0][jt], qf[0][1], kfr[1][jt], sc[0][jt]);
            mma_f16h(sc[1][jt], qf[1][1], kfr[1][jt], sc[1][jt]);
        }

        // V A-fragments (non-trans) — LDS latency hides under exp
        uint32_t va[2][2][4];
#pragma unroll
        for (int dvt = 0; dvt < 2; dvt++)
#pragma unroll
            for (int kk = 0; kk < 2; kk++) {
                uint32_t addrh = (uint32_t)((dvt * 16 + ((lane >> 3) & 1) * 8 + (lane & 7)) * 72
                                          + (jcol + kk * 16 + (lane >> 4) * 8));
                ldsm_x4(va[dvt][kk][0], va[dvt][kk][1], va[dvt][kk][2], va[dvt][kk][3],
                        su(Vs) + addrh * 2);
            }

        // P^T = 2^S : ex2.f16x2 directly on accumulator regs
        uint32_t pb[2][4][2];
#pragma unroll
        for (int kk = 0; kk < 2; kk++)
#pragma unroll
            for (int mt = 0; mt < 2; mt++) {
                pb[kk][2 * mt][0]     = ex2h2(sc[mt][2 * kk][0]);
                pb[kk][2 * mt][1]     = ex2h2(sc[mt][2 * kk + 1][0]);
                pb[kk][2 * mt + 1][0] = ex2h2(sc[mt][2 * kk][1]);
                pb[kk][2 * mt + 1][1] = ex2h2(sc[mt][2 * kk + 1][1]);
            }

        // Row sums on the FMA pipe
#pragma unroll
        for (int it = 0; it < 4; it++) {
            uint32_t hs = hadd2(hadd2(pb[0][it][0], pb[0][it][1]),
                                hadd2(pb[1][it][0], pb[1][it][1]));
            lsum[it] += h2sum(hs);
        }

        // O^T += V P^T (fp32 accum)
#pragma unroll
        for (int kk = 0; kk < 2; kk++)
#pragma unroll
            for (int it = 0; it < 4; it++) {
                mma_f16(oacc[0][it], va[0][kk], pb[kk][it]);
                mma_f16(oacc[1][it], va[1][kk], pb[kk][it]);
            }
    }

    // Quad-reduce row sums over t
#pragma unroll
    for (int it = 0; it < 4; it++) {
        lsum[it] += __shfl_xor_sync(0xffffffffu, lsum[it], 1);
        lsum[it] += __shfl_xor_sync(0xffffffffu, lsum[it], 2);
    }

    // Cross-jg reduction
    __syncthreads();
    if (t == 0) {
#pragma unroll
        for (int it = 0; it < 4; it++)
            redL[jg][rg][it * 8 + g] = lsum[it];
    }
    if (jg == 1) {
#pragma unroll
        for (int dvt = 0; dvt < 2; dvt++)
#pragma unroll
            for (int it = 0; it < 4; it++) {
                int dv = dvt * 16 + g, ii = it * 8 + 2 * t;
                redO[rg][dv][ii]         = oacc[dvt][it][0];
                redO[rg][dv][ii + 1]     = oacc[dvt][it][1];
                redO[rg][dv + 8][ii]     = oacc[dvt][it][2];
                redO[rg][dv + 8][ii + 1] = oacc[dvt][it][3];
            }
    }
    __syncthreads();
    if (jg == 0) {
        uint16_t* Ob = oh + ((size_t)b * 256 + h * 32) * NTOK;
#pragma unroll
        for (int it = 0; it < 4; it++) {
            int ii = it * 8 + 2 * t;
            float inv0 = 1.f / (redL[0][rg][ii] + redL[1][rg][ii]);
            float inv1 = 1.f / (redL[0][rg][ii + 1] + redL[1][rg][ii + 1]);
            int ig = i0 + ibase + ii;
#pragma unroll
            for (int dvt = 0; dvt < 2; dvt++) {
                int dv = dvt * 16 + g;
                float o0 = (oacc[dvt][it][0] + redO[rg][dv][ii]) * inv0;
                float o1 = (oacc[dvt][it][1] + redO[rg][dv][ii + 1]) * inv1;
                *(uint32_t*)&Ob[(size_t)dv * NTOK + ig] = f2h2(o0, o1);
                float o2 = (oacc[dvt][it][2] + redO[rg][dv + 8][ii]) * inv0;
                float o3 = (oacc[dvt][it][3] + redO[rg][dv + 8][ii + 1]) * inv1;
                *(uint32_t*)&Ob[(size_t)(dv + 8) * NTOK + ig] = f2h2(o2, o3);
            }
        }
    }
}

// ---------------------------------------------------------------------------

extern "C" void kernel_launch(void* const* d_in, const int* in_sizes, int n_in,
                              void* d_out, int out_size)
{
    const float* x     = (const float*)d_in[0];  // (4,256,48,48)
    const float* w_qkv = (const float*)d_in[1];  // (768,256)
    const float* w_out = (const float*)d_in[2];  // (256,256)
    const float* b_out = (const float*)d_in[3];  // (256)
    float* out = (float*)d_out;                  // (4,256,48,48)

    uint4 *wqkvF = nullptr, *woutF = nullptr, *qkvH = nullptr, *attnH = nullptr;
    cudaGetSymbolAddress((void**)&wqkvF, g_wqkv_frag);
    cudaGetSymbolAddress((void**)&woutF, g_wout_frag);
    cudaGetSymbolAddress((void**)&qkvH, g_qkv_h);
    cudaGetSymbolAddress((void**)&attnH, g_attn_h);

    const float qscale = 0.25507607192159975f;  // log2(e)/sqrt(32)
    const int g3_smem = 8 * 2176 * 4;           // 69632 B

    cudaFuncSetAttribute(gemm_f16b_kernel, cudaFuncAttributeMaxDynamicSharedMemorySize,
                         g3_smem);

    // 0) weight prep (fused)
    prep_frag_kernel<<<128, 256>>>(w_qkv, w_out, wqkvF, woutF, qscale);

    // 1) QKV projection (fp32 x -> fp16 qkv)  (864 CTAs)
    gemm_f32b_kernel<<<dim3(18, 12, 4), 256>>>(wqkvF, x, (uint16_t*)qkvH, NTOK, 256);
    // 2) Flash attention -> fp16 attn  (576 CTAs, 3 CTAs/SM)
    attn_kernel<<<dim3(18, 32), 256>>>((const uint16_t*)qkvH, (uint16_t*)attnH);
    // 3) Output projection + bias -> fp32 out  (288 CTAs)
    gemm_f16b_kernel<<<dim3(18, 4, 4), 256, g3_smem>>>(woutF, (const uint16_t*)attnH,
                                                       out, b_out, NTOK);
}